// round 1
// baseline (speedup 1.0000x reference)
#include <cuda_runtime.h>
#include <cuda_bf16.h>

#define NN 100000
#define EE 1600000
#define FN 128
#define FE 32
#define HID 128
#define OUTC 64

// ---------------- scratch (device globals; no allocation allowed) ----------
__device__ float4 g_agg [NN * (FE/4)];     // [N,32]  aggregated edge features
__device__ float  g_deg [NN];              // degree, then dinv in-place
__device__ float4 g_h1  [NN * (HID/4)];    // [N,128] h @ w1
__device__ float4 g_out1[NN * (HID/4)];    // [N,128] layer-1 output (pre-relu)
__device__ float4 g_h2  [NN * (OUTC/4)];   // [N,64]  h2 @ w2
__device__ int    g_is64;

// ---------------- helpers ---------------------------------------------------
__device__ __forceinline__ long long getidx(const void* ei, long long pos, int is64) {
    if (is64) return ((const long long*)ei)[pos];
    return (long long)((const int*)ei)[pos];
}

__device__ __forceinline__ void red4(float4* p, float4 v) {
    asm volatile("red.global.add.v4.f32 [%0], {%1,%2,%3,%4};"
                 :: "l"(p), "f"(v.x), "f"(v.y), "f"(v.z), "f"(v.w) : "memory");
}

// ---------------- dtype detection (int32 vs int64 edge_index) --------------
// If data is really int64, every 8-byte read is a valid node id in [0,N).
// If int32, an 8-byte read packs two ids: value = lo + hi*2^32 >= 2^32 unless
// hi==0 (p = 1e-5 per entry; 64 entries => p ~ 1e-320 of misdetection).
__global__ void detect_kernel(const void* ei) {
    if (threadIdx.x == 0 && blockIdx.x == 0) {
        const long long* p = (const long long*)ei;
        int is64 = 1;
        for (int i = 0; i < 64; ++i) {
            long long v = p[i];
            if (v < 0 || v >= NN) { is64 = 0; break; }
        }
        g_is64 = is64;
    }
}

// ---------------- init: agg = 0, deg = 1 (self-loop) ------------------------
__global__ void init_kernel() {
    long long tid = (long long)blockIdx.x * blockDim.x + threadIdx.x;
    if (tid < (long long)NN * (FE/4)) g_agg[tid] = make_float4(0.f, 0.f, 0.f, 0.f);
    if (tid < NN) g_deg[tid] = 1.0f;
}

// ---------------- edge pass 1: agg[row] += edge_attr, deg[col] += 1 --------
__global__ void edge_agg_kernel(const void* __restrict__ ei,
                                const float4* __restrict__ eattr) {
    long long tid = (long long)blockIdx.x * blockDim.x + threadIdx.x;
    if (tid >= (long long)EE * (FE/4)) return;
    const int c = (int)(tid & 7);
    const long long e = tid >> 3;
    const int is64 = g_is64;
    const long long row = getidx(ei, e, is64);
    red4(&g_agg[row * (FE/4) + c], eattr[e * (FE/4) + c]);
    if (c == 0) {
        const long long col = getidx(ei, EE + e, is64);
        atomicAdd(&g_deg[col], 1.0f);
    }
}

// ---------------- deg -> dinv ------------------------------------------------
__global__ void rsqrt_kernel() {
    long long tid = (long long)blockIdx.x * blockDim.x + threadIdx.x;
    if (tid < NN) g_deg[tid] = rsqrtf(g_deg[tid]);
}

// ---------------- GEMM: out[N,OC] = [A | agg] @ W  (K = CA+32) --------------
// 128 threads, 64-node tile. W and input tile staged in SMEM; inner product
// is smem-broadcast LDS + FFMA (FMA-pipe bound).
template <int OC, int CA, bool RELU>
__global__ void gemm_kernel(const float* __restrict__ A,
                            const float* __restrict__ W,
                            float* __restrict__ Out) {
    constexpr int K = CA + FE;
    constexpr int TN = 64;
    constexpr int THREADS = 128;
    constexpr int SEG = THREADS / OC;   // 1 (OC=128) or 2 (OC=64)
    constexpr int NPT = TN / SEG;       // nodes per thread: 64 or 32

    extern __shared__ float sm[];
    float* ws  = sm;            // K*OC
    float* ins = sm + K * OC;   // TN*K

    const int tid = threadIdx.x;
    const int c   = tid % OC;
    const int seg = tid / OC;
    const long long nb = (long long)blockIdx.x * TN;

    for (int idx = tid; idx < K * OC; idx += THREADS) ws[idx] = W[idx];

    for (int idx = tid; idx < TN * CA; idx += THREADS) {
        int n = idx / CA, k = idx % CA;
        long long node = nb + n;
        float v = 0.f;
        if (node < NN) {
            v = A[node * CA + k];
            if (RELU) v = fmaxf(v, 0.f);
        }
        ins[n * K + k] = v;
    }
    const float* aggf = (const float*)g_agg;
    for (int idx = tid; idx < TN * FE; idx += THREADS) {
        int n = idx / FE, k = idx % FE;
        long long node = nb + n;
        ins[n * K + CA + k] = (node < NN) ? aggf[node * FE + k] : 0.f;
    }
    __syncthreads();

    float acc[NPT];
#pragma unroll
    for (int n = 0; n < NPT; ++n) acc[n] = 0.f;

    const float* insrow = ins + (seg * NPT) * K;
    for (int k = 0; k < K; ++k) {
        const float wv = ws[k * OC + c];
#pragma unroll
        for (int n = 0; n < NPT; ++n)
            acc[n] = fmaf(insrow[n * K + k], wv, acc[n]);
    }

#pragma unroll
    for (int n = 0; n < NPT; ++n) {
        long long node = nb + seg * NPT + n;
        if (node < NN) Out[node * OC + c] = acc[n];
    }
}

// ---------------- out = b + dinv^2 * h  (self-loop term + bias) -------------
template <int C>
__global__ void self_bias_kernel(const float* __restrict__ h,
                                 const float* __restrict__ b,
                                 float* __restrict__ out) {
    long long tid = (long long)blockIdx.x * blockDim.x + threadIdx.x;
    if (tid >= (long long)NN * C) return;
    const long long n = tid / C;
    const int j = (int)(tid % C);
    const float d = g_deg[n];
    out[tid] = fmaf(d * d, h[tid], b[j]);
}

// ---------------- message scatter: out[col] += h[row]*dinv[row]*dinv[col] ---
template <int VPE>  // float4s per edge (32 for 128-dim, 16 for 64-dim)
__global__ void edge_scatter_kernel(const void* __restrict__ ei,
                                    const float4* __restrict__ src,
                                    float4* __restrict__ dst) {
    long long tid = (long long)blockIdx.x * blockDim.x + threadIdx.x;
    if (tid >= (long long)EE * VPE) return;
    const int c = (int)(tid % VPE);
    const long long e = tid / VPE;
    const int is64 = g_is64;
    const long long row = getidx(ei, e, is64);
    const long long col = getidx(ei, EE + e, is64);
    const float coeff = g_deg[row] * g_deg[col];
    float4 v = src[row * VPE + c];
    v.x *= coeff; v.y *= coeff; v.z *= coeff; v.w *= coeff;
    red4(dst + col * VPE + c, v);
}

// ---------------- launch -----------------------------------------------------
extern "C" void kernel_launch(void* const* d_in, const int* in_sizes, int n_in,
                              void* d_out, int out_size) {
    const float* x     = (const float*)d_in[0];
    const void*  ei    = d_in[1];                 // int32 or int64, detected on-device
    const float4* eatt = (const float4*)d_in[2];
    const float* w1    = (const float*)d_in[3];
    const float* b1    = (const float*)d_in[4];
    const float* w2    = (const float*)d_in[5];
    const float* b2    = (const float*)d_in[6];
    float* out = (float*)d_out;

    constexpr int T = 256;
    const int smem1 = (160 * 128 + 64 * 160) * 4;  // 122880 B
    const int smem2 = (160 * 64 + 64 * 160) * 4;   //  81920 B
    cudaFuncSetAttribute(gemm_kernel<HID, FN, false>,
                         cudaFuncAttributeMaxDynamicSharedMemorySize, smem1);
    cudaFuncSetAttribute(gemm_kernel<OUTC, HID, true>,
                         cudaFuncAttributeMaxDynamicSharedMemorySize, smem2);

    detect_kernel<<<1, 32>>>(ei);

    {   // init agg + deg
        long long n = (long long)NN * (FE / 4);
        init_kernel<<<(unsigned)((n + T - 1) / T), T>>>();
    }
    {   // agg[row] += edge_attr ; deg[col] += 1
        long long n = (long long)EE * (FE / 4);
        edge_agg_kernel<<<(unsigned)((n + T - 1) / T), T>>>(ei, eatt);
    }
    rsqrt_kernel<<<(NN + T - 1) / T, T>>>();

    const unsigned gblocks = (NN + 63) / 64;  // 1563

    // layer 1
    gemm_kernel<HID, FN, false><<<gblocks, 128, smem1>>>(x, w1, (float*)g_h1);
    {
        long long n = (long long)NN * HID;
        self_bias_kernel<HID><<<(unsigned)((n + T - 1) / T), T>>>(
            (const float*)g_h1, b1, (float*)g_out1);
    }
    {
        long long n = (long long)EE * (HID / 4);
        edge_scatter_kernel<HID / 4><<<(unsigned)((n + T - 1) / T), T>>>(
            ei, g_h1, g_out1);
    }

    // layer 2 (relu folded into GEMM input load)
    gemm_kernel<OUTC, HID, true><<<gblocks, 128, smem2>>>(
        (const float*)g_out1, w2, (float*)g_h2);
    {
        long long n = (long long)NN * OUTC;
        self_bias_kernel<OUTC><<<(unsigned)((n + T - 1) / T), T>>>(
            (const float*)g_h2, b2, out);
    }
    {
        long long n = (long long)EE * (OUTC / 4);
        edge_scatter_kernel<OUTC / 4><<<(unsigned)((n + T - 1) / T), T>>>(
            ei, g_h2, (float4*)out);
    }
}

// round 3
// speedup vs baseline: 1.6220x; 1.6220x over previous
#include <cuda_runtime.h>
#include <cuda_bf16.h>

#define NN 100000
#define EE 1600000
#define FN 128
#define FE 32
#define HID 128
#define OUTC 64

// ---------------- scratch (device globals; no allocation allowed) ----------
__device__ float4 g_agg [NN * (FE/4)];     // [N,32]  aggregated edge features
__device__ float  g_deg [NN];              // dinv
__device__ float4 g_h1  [NN * (HID/4)];    // [N,128] h @ w1
__device__ float4 g_out1[NN * (HID/4)];    // [N,128] layer-1 output
__device__ float4 g_h2  [NN * (OUTC/4)];   // [N,64]  h2 @ w2
__device__ int    g_is64;

__device__ int g_cnt_row[NN];
__device__ int g_cnt_col[NN];
__device__ int g_cur_row[NN];
__device__ int g_cur_col[NN];
__device__ int g_base_row[NN + 1];
__device__ int g_base_col[NN + 1];
__device__ int g_csr_row_e [EE];   // edge ids sorted by row  (for agg gather)
__device__ int g_csr_col_src[EE];  // src node ids sorted by col (for msg gather)

// ---------------- helpers ---------------------------------------------------
__device__ __forceinline__ long long getidx(const void* ei, long long pos, int is64) {
    if (is64) return ((const long long*)ei)[pos];
    return (long long)((const int*)ei)[pos];
}

// ---------------- dtype detection (int32 vs int64 edge_index) --------------
__global__ __launch_bounds__(32) void detect_kernel(const void* ei) {
    if (threadIdx.x == 0 && blockIdx.x == 0) {
        const long long* p = (const long long*)ei;
        int is64 = 1;
        for (int i = 0; i < 64; ++i) {
            long long v = p[i];
            if (v < 0 || v >= NN) { is64 = 0; break; }
        }
        g_is64 = is64;
    }
}

// ---------------- zero counters ---------------------------------------------
__global__ __launch_bounds__(256) void zero_kernel() {
    int tid = blockIdx.x * blockDim.x + threadIdx.x;
    if (tid < NN) {
        g_cnt_row[tid] = 0; g_cnt_col[tid] = 0;
        g_cur_row[tid] = 0; g_cur_col[tid] = 0;
    }
}

// ---------------- degree histograms ------------------------------------------
__global__ __launch_bounds__(256) void hist_kernel(const void* __restrict__ ei) {
    long long e = (long long)blockIdx.x * blockDim.x + threadIdx.x;
    if (e >= EE) return;
    const int is64 = g_is64;
    atomicAdd(&g_cnt_row[(int)getidx(ei, e, is64)], 1);
    atomicAdd(&g_cnt_col[(int)getidx(ei, EE + e, is64)], 1);
}

// ---------------- exclusive scan (one block per array) -----------------------
__global__ __launch_bounds__(1024, 1) void scan_kernel() {
    const int* cnt = (blockIdx.x == 0) ? g_cnt_row : g_cnt_col;
    int* base      = (blockIdx.x == 0) ? g_base_row : g_base_col;
    const int t = threadIdx.x;
    constexpr int PER = (NN + 1023) / 1024;   // 98
    const int beg = t * PER;
    int s = 0;
#pragma unroll 1
    for (int i = 0; i < PER; ++i) {
        int idx = beg + i;
        if (idx < NN) s += cnt[idx];
    }
    __shared__ int sm[1024];
    sm[t] = s;
    __syncthreads();
    for (int off = 1; off < 1024; off <<= 1) {
        int u = (t >= off) ? sm[t - off] : 0;
        __syncthreads();
        sm[t] += u;
        __syncthreads();
    }
    int run = sm[t] - s;   // exclusive prefix
#pragma unroll 1
    for (int i = 0; i < PER; ++i) {
        int idx = beg + i;
        if (idx < NN) { base[idx] = run; run += cnt[idx]; }
    }
    if (t == 1023) base[NN] = run;
}

// ---------------- dinv = rsqrt(in_degree + 1) --------------------------------
__global__ __launch_bounds__(256) void dinv_kernel() {
    int tid = blockIdx.x * blockDim.x + threadIdx.x;
    if (tid < NN) g_deg[tid] = rsqrtf((float)(g_cnt_col[tid] + 1));
}

// ---------------- build both CSRs --------------------------------------------
__global__ __launch_bounds__(256) void reorder_kernel(const void* __restrict__ ei) {
    long long e = (long long)blockIdx.x * blockDim.x + threadIdx.x;
    if (e >= EE) return;
    const int is64 = g_is64;
    const int r = (int)getidx(ei, e, is64);
    const int c = (int)getidx(ei, EE + e, is64);
    int p = atomicAdd(&g_cur_row[r], 1);
    g_csr_row_e[g_base_row[r] + p] = (int)e;
    int q = atomicAdd(&g_cur_col[c], 1);
    g_csr_col_src[g_base_col[c] + q] = r;
}

// ---------------- agg[n] = sum edge_attr over edges with row==n --------------
// warp per node: lanes split 8 float4-cols x 4 edge groups
__global__ __launch_bounds__(256) void agg_gather_kernel(const float4* __restrict__ eattr) {
    const int warp = (blockIdx.x * blockDim.x + threadIdx.x) >> 5;
    if (warp >= NN) return;
    const int lane = threadIdx.x & 31;
    const int c = lane & 7;
    const int g = lane >> 3;
    const int beg = g_base_row[warp], end = g_base_row[warp + 1];
    float4 acc = make_float4(0.f, 0.f, 0.f, 0.f);
    for (int i = beg + g; i < end; i += 4) {
        const int e = g_csr_row_e[i];
        const float4 v = eattr[(long long)e * 8 + c];
        acc.x += v.x; acc.y += v.y; acc.z += v.z; acc.w += v.w;
    }
#pragma unroll
    for (int off = 8; off <= 16; off <<= 1) {
        acc.x += __shfl_xor_sync(0xffffffffu, acc.x, off);
        acc.y += __shfl_xor_sync(0xffffffffu, acc.y, off);
        acc.z += __shfl_xor_sync(0xffffffffu, acc.z, off);
        acc.w += __shfl_xor_sync(0xffffffffu, acc.w, off);
    }
    if (lane < 8) g_agg[warp * 8 + c] = acc;
}

// ---------------- GEMM: out[N,OC] = [A | agg] @ W  (K = CA+32) ---------------
template <int OC, int CA, bool RELU>
__global__ __launch_bounds__(128) void gemm_kernel(const float* __restrict__ A,
                            const float* __restrict__ W,
                            float* __restrict__ Out) {
    constexpr int K = CA + FE;
    constexpr int TN = 64;
    constexpr int THREADS = 128;
    constexpr int SEG = THREADS / OC;
    constexpr int NPT = TN / SEG;

    extern __shared__ float sm[];
    float* ws  = sm;            // K*OC
    float* ins = sm + K * OC;   // TN*K

    const int tid = threadIdx.x;
    const int c   = tid % OC;
    const int seg = tid / OC;
    const long long nb = (long long)blockIdx.x * TN;

    for (int idx = tid; idx < K * OC; idx += THREADS) ws[idx] = W[idx];

    for (int idx = tid; idx < TN * CA; idx += THREADS) {
        int n = idx / CA, k = idx % CA;
        long long node = nb + n;
        float v = 0.f;
        if (node < NN) {
            v = A[node * CA + k];
            if (RELU) v = fmaxf(v, 0.f);
        }
        ins[n * K + k] = v;
    }
    const float* aggf = (const float*)g_agg;
    for (int idx = tid; idx < TN * FE; idx += THREADS) {
        int n = idx / FE, k = idx % FE;
        long long node = nb + n;
        ins[n * K + CA + k] = (node < NN) ? aggf[node * FE + k] : 0.f;
    }
    __syncthreads();

    float acc[NPT];
#pragma unroll
    for (int n = 0; n < NPT; ++n) acc[n] = 0.f;

    const float* insrow = ins + (seg * NPT) * K;
    for (int k = 0; k < K; ++k) {
        const float wv = ws[k * OC + c];
#pragma unroll
        for (int n = 0; n < NPT; ++n)
            acc[n] = fmaf(insrow[n * K + k], wv, acc[n]);
    }

#pragma unroll
    for (int n = 0; n < NPT; ++n) {
        long long node = nb + seg * NPT + n;
        if (node < NN) Out[node * OC + c] = acc[n];
    }
}

// ---------------- layer gather, 128-dim: warp per node -----------------------
// out[n] = b + dinv[n]*sum(dinv[s]*h[s]) + dinv[n]^2*h[n]
__global__ __launch_bounds__(256) void gather128_kernel(const float4* __restrict__ h,
                                 const float*  __restrict__ bias,
                                 float4* __restrict__ out) {
    const int n = (blockIdx.x * blockDim.x + threadIdx.x) >> 5;
    if (n >= NN) return;
    const int lane = threadIdx.x & 31;
    const int beg = g_base_col[n], end = g_base_col[n + 1];
    float4 acc = make_float4(0.f, 0.f, 0.f, 0.f);
    for (int i0 = beg; i0 < end; i0 += 32) {
        const int slot = i0 + lane;
        int s = 0; float w = 0.f;
        if (slot < end) { s = g_csr_col_src[slot]; w = g_deg[s]; }
        const int m = min(32, end - i0);
        for (int j = 0; j < m; ++j) {
            const int   sj = __shfl_sync(0xffffffffu, s, j);
            const float wj = __shfl_sync(0xffffffffu, w, j);
            const float4 v = h[(long long)sj * 32 + lane];
            acc.x = fmaf(wj, v.x, acc.x);
            acc.y = fmaf(wj, v.y, acc.y);
            acc.z = fmaf(wj, v.z, acc.z);
            acc.w = fmaf(wj, v.w, acc.w);
        }
    }
    const float dn = g_deg[n];
    const float d2 = dn * dn;
    const float4 self = h[(long long)n * 32 + lane];
    const float4 bb = ((const float4*)bias)[lane];
    float4 o;
    o.x = bb.x + dn * acc.x + d2 * self.x;
    o.y = bb.y + dn * acc.y + d2 * self.y;
    o.z = bb.z + dn * acc.z + d2 * self.z;
    o.w = bb.w + dn * acc.w + d2 * self.w;
    out[(long long)n * 32 + lane] = o;
}

// ---------------- layer gather, 64-dim: warp per node, 2 edges/iter ----------
__global__ __launch_bounds__(256) void gather64_kernel(const float4* __restrict__ h,
                                const float*  __restrict__ bias,
                                float4* __restrict__ out) {
    const int n = (blockIdx.x * blockDim.x + threadIdx.x) >> 5;
    if (n >= NN) return;
    const int lane = threadIdx.x & 31;
    const int c = lane & 15;
    const int g = lane >> 4;
    const int beg = g_base_col[n], end = g_base_col[n + 1];
    float4 acc = make_float4(0.f, 0.f, 0.f, 0.f);
    for (int i0 = beg; i0 < end; i0 += 32) {
        const int slot = i0 + lane;
        int s = 0; float w = 0.f;
        if (slot < end) { s = g_csr_col_src[slot]; w = g_deg[s]; }
        const int m = min(32, end - i0);
        for (int j = 0; j < m; j += 2) {
            const int idx = j + g;           // lanes beyond m have w=0, contribute 0
            const int   sj = __shfl_sync(0xffffffffu, s, idx);
            const float wj = __shfl_sync(0xffffffffu, w, idx);
            const float4 v = h[(long long)sj * 16 + c];
            acc.x = fmaf(wj, v.x, acc.x);
            acc.y = fmaf(wj, v.y, acc.y);
            acc.z = fmaf(wj, v.z, acc.z);
            acc.w = fmaf(wj, v.w, acc.w);
        }
    }
    acc.x += __shfl_xor_sync(0xffffffffu, acc.x, 16);
    acc.y += __shfl_xor_sync(0xffffffffu, acc.y, 16);
    acc.z += __shfl_xor_sync(0xffffffffu, acc.z, 16);
    acc.w += __shfl_xor_sync(0xffffffffu, acc.w, 16);
    if (lane < 16) {
        const float dn = g_deg[n];
        const float d2 = dn * dn;
        const float4 self = h[(long long)n * 16 + c];
        const float4 bb = ((const float4*)bias)[c];
        float4 o;
        o.x = bb.x + dn * acc.x + d2 * self.x;
        o.y = bb.y + dn * acc.y + d2 * self.y;
        o.z = bb.z + dn * acc.z + d2 * self.z;
        o.w = bb.w + dn * acc.w + d2 * self.w;
        out[(long long)n * 16 + c] = o;
    }
}

// ---------------- launch -----------------------------------------------------
extern "C" void kernel_launch(void* const* d_in, const int* in_sizes, int n_in,
                              void* d_out, int out_size) {
    const float*  x    = (const float*)d_in[0];
    const void*   ei   = d_in[1];
    const float4* eatt = (const float4*)d_in[2];
    const float*  w1   = (const float*)d_in[3];
    const float*  b1   = (const float*)d_in[4];
    const float*  w2   = (const float*)d_in[5];
    const float*  b2   = (const float*)d_in[6];
    float* out = (float*)d_out;

    constexpr int T = 256;
    const int smem1 = (160 * 128 + 64 * 160) * 4;  // 122880 B
    const int smem2 = (160 * 64 + 64 * 160) * 4;   //  81920 B
    cudaFuncSetAttribute(gemm_kernel<HID, FN, false>,
                         cudaFuncAttributeMaxDynamicSharedMemorySize, smem1);
    cudaFuncSetAttribute(gemm_kernel<OUTC, HID, true>,
                         cudaFuncAttributeMaxDynamicSharedMemorySize, smem2);

    detect_kernel<<<1, 32>>>(ei);
    zero_kernel<<<(NN + T - 1) / T, T>>>();
    hist_kernel<<<(EE + T - 1) / T, T>>>(ei);
    scan_kernel<<<2, 1024>>>();
    dinv_kernel<<<(NN + T - 1) / T, T>>>();
    reorder_kernel<<<(EE + T - 1) / T, T>>>(ei);

    const unsigned wblocks = (NN * 32 + T - 1) / T;   // warp per node
    agg_gather_kernel<<<wblocks, T>>>(eatt);

    const unsigned gblocks = (NN + 63) / 64;  // 1563

    // layer 1
    gemm_kernel<HID, FN, false><<<gblocks, 128, smem1>>>(x, w1, (float*)g_h1);
    gather128_kernel<<<wblocks, T>>>(g_h1, b1, g_out1);

    // layer 2 (relu folded into GEMM input load)
    gemm_kernel<OUTC, HID, true><<<gblocks, 128, smem2>>>(
        (const float*)g_out1, w2, (float*)g_h2);
    gather64_kernel<<<wblocks, T>>>(g_h2, b2, (float4*)out);
}

// round 4
// speedup vs baseline: 1.6976x; 1.0467x over previous
#include <cuda_runtime.h>
#include <cuda_bf16.h>

#define NN 100000
#define EE 1600000
#define FN 128
#define FE 32
#define HID 128
#define OUTC 64
#define PADN 102400   // NN padded to multiple of 4096 (1024 threads * 4)

// ---------------- scratch (device globals; no allocation allowed) ----------
__device__ float4 g_agg [NN * (FE/4)];     // [N,32]  aggregated edge features
__device__ float4 g_deg4[PADN/4];          // dinv (padded, vector-aligned)
__device__ float4 g_h1  [NN * (HID/4)];    // [N,128] h @ w1
__device__ float4 g_out1[NN * (HID/4)];    // [N,128] layer-1 output
__device__ float4 g_h2  [NN * (OUTC/4)];   // [N,64]  h2 @ w2
__device__ int    g_is64;

__device__ int4 g_cnt_row4[PADN/4];
__device__ int4 g_cnt_col4[PADN/4];
__device__ int  g_cur_row[NN];
__device__ int  g_cur_col[NN];
__device__ int4 g_base_row4[PADN/4 + 1];
__device__ int4 g_base_col4[PADN/4 + 1];
__device__ int  g_csr_row_e  [EE];  // edge ids sorted by row  (for agg gather)
__device__ int  g_csr_col_src[EE];  // src node ids sorted by col (for msg gather)

#define g_deg      ((float*)g_deg4)
#define g_cnt_row  ((int*)g_cnt_row4)
#define g_cnt_col  ((int*)g_cnt_col4)
#define g_base_row ((int*)g_base_row4)
#define g_base_col ((int*)g_base_col4)

// ---------------- helpers ---------------------------------------------------
__device__ __forceinline__ long long getidx(const void* ei, long long pos, int is64) {
    if (is64) return ((const long long*)ei)[pos];
    return (long long)((const int*)ei)[pos];
}

// ---------------- fused: zero counters + dtype detection --------------------
__global__ __launch_bounds__(256) void detect_zero_kernel(const void* ei) {
    int tid = blockIdx.x * blockDim.x + threadIdx.x;
    if (tid < PADN) { g_cnt_row[tid] = 0; g_cnt_col[tid] = 0; }
    if (tid < NN)   { g_cur_row[tid] = 0; g_cur_col[tid] = 0; }
    if (blockIdx.x == 0 && threadIdx.x == 0) {
        const longlong4* p = (const longlong4*)ei;   // 64 int64 (or 128 int32) probe
        int ok = 1;
#pragma unroll
        for (int i = 0; i < 16; ++i) {
            longlong4 v = p[i];
            ok &= (v.x >= 0 && v.x < NN) & (v.y >= 0 && v.y < NN)
                & (v.z >= 0 && v.z < NN) & (v.w >= 0 && v.w < NN);
        }
        g_is64 = ok;
    }
}

// ---------------- degree histograms ------------------------------------------
__global__ __launch_bounds__(256) void hist_kernel(const void* __restrict__ ei) {
    long long e = (long long)blockIdx.x * blockDim.x + threadIdx.x;
    if (e >= EE) return;
    const int is64 = g_is64;
    atomicAdd(&g_cnt_row[(int)getidx(ei, e, is64)], 1);
    atomicAdd(&g_cnt_col[(int)getidx(ei, EE + e, is64)], 1);
}

// ---------------- exclusive scan + dinv (one block per array) ---------------
__global__ __launch_bounds__(1024, 1) void scan_kernel() {
    const int4* c4 = (blockIdx.x == 0) ? g_cnt_row4 : g_cnt_col4;
    int4* b4       = (blockIdx.x == 0) ? g_base_row4 : g_base_col4;
    const int t = threadIdx.x;
    constexpr int PER4 = PADN / 4 / 1024;   // 25 int4 per thread

    int s = 0;
#pragma unroll
    for (int i = 0; i < PER4; ++i) {
        int4 q = c4[t * PER4 + i];
        s += q.x + q.y + q.z + q.w;
    }
    __shared__ int sm[1024];
    sm[t] = s;
    __syncthreads();
    for (int off = 1; off < 1024; off <<= 1) {
        int u = (t >= off) ? sm[t - off] : 0;
        __syncthreads();
        sm[t] += u;
        __syncthreads();
    }
    int run = sm[t] - s;   // exclusive prefix
#pragma unroll
    for (int i = 0; i < PER4; ++i) {
        int4 q = c4[t * PER4 + i];
        int4 b;
        b.x = run;
        b.y = b.x + q.x;
        b.z = b.y + q.y;
        b.w = b.z + q.z;
        run = b.w + q.w;
        b4[t * PER4 + i] = b;
    }
    if (blockIdx.x == 1) {   // dinv = rsqrt(in_degree + 1), fused here
#pragma unroll
        for (int i = 0; i < PER4; ++i) {
            int4 q = c4[t * PER4 + i];
            float4 d;
            d.x = rsqrtf((float)(q.x + 1));
            d.y = rsqrtf((float)(q.y + 1));
            d.z = rsqrtf((float)(q.z + 1));
            d.w = rsqrtf((float)(q.w + 1));
            g_deg4[t * PER4 + i] = d;
        }
    }
}

// ---------------- build both CSRs (profiled slot #4) -------------------------
__global__ __launch_bounds__(256) void reorder_kernel(const void* __restrict__ ei) {
    long long e = (long long)blockIdx.x * blockDim.x + threadIdx.x;
    if (e >= EE) return;
    const int is64 = g_is64;
    const int r = (int)getidx(ei, e, is64);
    const int c = (int)getidx(ei, EE + e, is64);
    int p = atomicAdd(&g_cur_row[r], 1);
    g_csr_row_e[g_base_row[r] + p] = (int)e;
    int q = atomicAdd(&g_cur_col[c], 1);
    g_csr_col_src[g_base_col[c] + q] = r;
}

// ---------------- agg[n] = sum edge_attr over edges with row==n --------------
// warp per node: lanes split 8 float4-cols x 4 edge groups; 2-way unroll (MLP 2x4)
__global__ __launch_bounds__(256) void agg_gather_kernel(const float4* __restrict__ eattr) {
    const int warp = (blockIdx.x * blockDim.x + threadIdx.x) >> 5;
    if (warp >= NN) return;
    const int lane = threadIdx.x & 31;
    const int c = lane & 7;
    const int g = lane >> 3;
    const int beg = g_base_row[warp], end = g_base_row[warp + 1];
    float4 a0 = make_float4(0.f, 0.f, 0.f, 0.f);
    float4 a1 = make_float4(0.f, 0.f, 0.f, 0.f);
    int i = beg + g;
    for (; i + 4 < end; i += 8) {
        const int e0 = g_csr_row_e[i];
        const int e1 = g_csr_row_e[i + 4];
        const float4 v0 = eattr[(long long)e0 * 8 + c];
        const float4 v1 = eattr[(long long)e1 * 8 + c];
        a0.x += v0.x; a0.y += v0.y; a0.z += v0.z; a0.w += v0.w;
        a1.x += v1.x; a1.y += v1.y; a1.z += v1.z; a1.w += v1.w;
    }
    if (i < end) {
        const float4 v = eattr[(long long)g_csr_row_e[i] * 8 + c];
        a0.x += v.x; a0.y += v.y; a0.z += v.z; a0.w += v.w;
    }
    a0.x += a1.x; a0.y += a1.y; a0.z += a1.z; a0.w += a1.w;
#pragma unroll
    for (int off = 8; off <= 16; off <<= 1) {
        a0.x += __shfl_xor_sync(0xffffffffu, a0.x, off);
        a0.y += __shfl_xor_sync(0xffffffffu, a0.y, off);
        a0.z += __shfl_xor_sync(0xffffffffu, a0.z, off);
        a0.w += __shfl_xor_sync(0xffffffffu, a0.w, off);
    }
    if (lane < 8) g_agg[warp * 8 + c] = a0;
}

// ---------------- GEMM: out[N,OC] = [A | agg] @ W  (K = CA+32) ---------------
// 256 threads; inputs staged in smem row-major [n][K]; inner loop vectorized
// along k (LDS.128 broadcast + 4 FFMA). Weight reads conflict-free scalar LDS.
template <int OC, int CA, bool RELU>
__global__ __launch_bounds__(256) void gemm_kernel(const float* __restrict__ A,
                                                   const float* __restrict__ W,
                                                   float* __restrict__ Out) {
    constexpr int K = CA + FE;
    constexpr int K4 = K / 4;
    constexpr int CA4 = CA / 4;
    constexpr int TN = 64;
    constexpr int THREADS = 256;
    constexpr int SEG = THREADS / OC;    // 2 (OC=128) or 4 (OC=64)
    constexpr int NPT = TN / SEG;        // 32 or 16

    extern __shared__ float sm[];
    float* ws = sm;                      // K*OC
    float4* ins4 = (float4*)(sm + K * OC);  // TN*K floats

    const int tid = threadIdx.x;
    const long long nb = (long long)blockIdx.x * TN;

    const float4* W4 = (const float4*)W;
    float4* ws4 = (float4*)ws;
    for (int idx = tid; idx < K * OC / 4; idx += THREADS) ws4[idx] = W4[idx];

    const float4* A4 = (const float4*)A;
    for (int idx = tid; idx < TN * CA4; idx += THREADS) {
        int n = idx / CA4, kk = idx % CA4;
        long long node = nb + n;
        float4 v = make_float4(0.f, 0.f, 0.f, 0.f);
        if (node < NN) {
            v = A4[node * CA4 + kk];
            if (RELU) {
                v.x = fmaxf(v.x, 0.f); v.y = fmaxf(v.y, 0.f);
                v.z = fmaxf(v.z, 0.f); v.w = fmaxf(v.w, 0.f);
            }
        }
        ins4[n * K4 + kk] = v;
    }
    for (int idx = tid; idx < TN * 8; idx += THREADS) {
        int n = idx / 8, kk = idx % 8;
        long long node = nb + n;
        ins4[n * K4 + CA4 + kk] =
            (node < NN) ? g_agg[node * 8 + kk] : make_float4(0.f, 0.f, 0.f, 0.f);
    }
    __syncthreads();

    const int c   = tid % OC;
    const int seg = tid / OC;
    float acc[NPT];
#pragma unroll
    for (int n = 0; n < NPT; ++n) acc[n] = 0.f;

    const float4* row = ins4 + (seg * NPT) * K4;
#pragma unroll 2
    for (int k4 = 0; k4 < K4; ++k4) {
        const float w0 = ws[(k4 * 4 + 0) * OC + c];
        const float w1 = ws[(k4 * 4 + 1) * OC + c];
        const float w2 = ws[(k4 * 4 + 2) * OC + c];
        const float w3 = ws[(k4 * 4 + 3) * OC + c];
#pragma unroll
        for (int n = 0; n < NPT; ++n) {
            const float4 iv = row[n * K4 + k4];
            float a = acc[n];
            a = fmaf(iv.x, w0, a);
            a = fmaf(iv.y, w1, a);
            a = fmaf(iv.z, w2, a);
            a = fmaf(iv.w, w3, a);
            acc[n] = a;
        }
    }

#pragma unroll
    for (int n = 0; n < NPT; ++n) {
        long long node = nb + seg * NPT + n;
        if (node < NN) Out[node * OC + c] = acc[n];
    }
}

// ---------------- layer gather, 128-dim: warp per node, 4 edges in flight ----
// out[n] = b + dinv[n]*sum(dinv[s]*h[s]) + dinv[n]^2*h[n]
// Lanes past the batch end carry (s=0, w=0) so over-read edges contribute 0 —
// no remainder loop, no divergence; indices stay < 32.
__global__ __launch_bounds__(256) void gather128_kernel(const float4* __restrict__ h,
                                                        const float* __restrict__ bias,
                                                        float4* __restrict__ out) {
    const int n = (blockIdx.x * blockDim.x + threadIdx.x) >> 5;
    if (n >= NN) return;
    const int lane = threadIdx.x & 31;
    const int beg = g_base_col[n], end = g_base_col[n + 1];
    float4 acc0 = make_float4(0.f, 0.f, 0.f, 0.f);
    float4 acc1 = make_float4(0.f, 0.f, 0.f, 0.f);
    for (int i0 = beg; i0 < end; i0 += 32) {
        const int slot = i0 + lane;
        int s = 0; float w = 0.f;
        if (slot < end) { s = g_csr_col_src[slot]; w = g_deg[s]; }
        const int m = min(32, end - i0);
        for (int j = 0; j < m; j += 4) {
            const int   s0 = __shfl_sync(0xffffffffu, s, j);
            const int   s1 = __shfl_sync(0xffffffffu, s, j + 1);
            const int   s2 = __shfl_sync(0xffffffffu, s, j + 2);
            const int   s3 = __shfl_sync(0xffffffffu, s, j + 3);
            const float w0 = __shfl_sync(0xffffffffu, w, j);
            const float w1 = __shfl_sync(0xffffffffu, w, j + 1);
            const float w2 = __shfl_sync(0xffffffffu, w, j + 2);
            const float w3 = __shfl_sync(0xffffffffu, w, j + 3);
            const float4 v0 = h[(long long)s0 * 32 + lane];
            const float4 v1 = h[(long long)s1 * 32 + lane];
            const float4 v2 = h[(long long)s2 * 32 + lane];
            const float4 v3 = h[(long long)s3 * 32 + lane];
            acc0.x = fmaf(w0, v0.x, acc0.x); acc0.y = fmaf(w0, v0.y, acc0.y);
            acc0.z = fmaf(w0, v0.z, acc0.z); acc0.w = fmaf(w0, v0.w, acc0.w);
            acc1.x = fmaf(w1, v1.x, acc1.x); acc1.y = fmaf(w1, v1.y, acc1.y);
            acc1.z = fmaf(w1, v1.z, acc1.z); acc1.w = fmaf(w1, v1.w, acc1.w);
            acc0.x = fmaf(w2, v2.x, acc0.x); acc0.y = fmaf(w2, v2.y, acc0.y);
            acc0.z = fmaf(w2, v2.z, acc0.z); acc0.w = fmaf(w2, v2.w, acc0.w);
            acc1.x = fmaf(w3, v3.x, acc1.x); acc1.y = fmaf(w3, v3.y, acc1.y);
            acc1.z = fmaf(w3, v3.z, acc1.z); acc1.w = fmaf(w3, v3.w, acc1.w);
        }
    }
    acc0.x += acc1.x; acc0.y += acc1.y; acc0.z += acc1.z; acc0.w += acc1.w;
    const float dn = g_deg[n];
    const float d2 = dn * dn;
    const float4 self = h[(long long)n * 32 + lane];
    const float4 bb = ((const float4*)bias)[lane];
    float4 o;
    o.x = bb.x + dn * acc0.x + d2 * self.x;
    o.y = bb.y + dn * acc0.y + d2 * self.y;
    o.z = bb.z + dn * acc0.z + d2 * self.z;
    o.w = bb.w + dn * acc0.w + d2 * self.w;
    out[(long long)n * 32 + lane] = o;
}

// ---------------- layer gather, 64-dim: warp per node, 8 edges per chunk -----
// Half-warps (g = 0/1) each handle 4 of the 8 edges -> MLP 4 per half-warp.
__global__ __launch_bounds__(256) void gather64_kernel(const float4* __restrict__ h,
                                                       const float* __restrict__ bias,
                                                       float4* __restrict__ out) {
    const int n = (blockIdx.x * blockDim.x + threadIdx.x) >> 5;
    if (n >= NN) return;
    const int lane = threadIdx.x & 31;
    const int c = lane & 15;
    const int g = lane >> 4;
    const int beg = g_base_col[n], end = g_base_col[n + 1];
    float4 acc0 = make_float4(0.f, 0.f, 0.f, 0.f);
    float4 acc1 = make_float4(0.f, 0.f, 0.f, 0.f);
    for (int i0 = beg; i0 < end; i0 += 32) {
        const int slot = i0 + lane;
        int s = 0; float w = 0.f;
        if (slot < end) { s = g_csr_col_src[slot]; w = g_deg[s]; }
        const int m = min(32, end - i0);
        for (int j = 0; j < m; j += 8) {
            const int   s0 = __shfl_sync(0xffffffffu, s, j + g);
            const int   s1 = __shfl_sync(0xffffffffu, s, j + 2 + g);
            const int   s2 = __shfl_sync(0xffffffffu, s, j + 4 + g);
            const int   s3 = __shfl_sync(0xffffffffu, s, j + 6 + g);
            const float w0 = __shfl_sync(0xffffffffu, w, j + g);
            const float w1 = __shfl_sync(0xffffffffu, w, j + 2 + g);
            const float w2 = __shfl_sync(0xffffffffu, w, j + 4 + g);
            const float w3 = __shfl_sync(0xffffffffu, w, j + 6 + g);
            const float4 v0 = h[(long long)s0 * 16 + c];
            const float4 v1 = h[(long long)s1 * 16 + c];
            const float4 v2 = h[(long long)s2 * 16 + c];
            const float4 v3 = h[(long long)s3 * 16 + c];
            acc0.x = fmaf(w0, v0.x, acc0.x); acc0.y = fmaf(w0, v0.y, acc0.y);
            acc0.z = fmaf(w0, v0.z, acc0.z); acc0.w = fmaf(w0, v0.w, acc0.w);
            acc1.x = fmaf(w1, v1.x, acc1.x); acc1.y = fmaf(w1, v1.y, acc1.y);
            acc1.z = fmaf(w1, v1.z, acc1.z); acc1.w = fmaf(w1, v1.w, acc1.w);
            acc0.x = fmaf(w2, v2.x, acc0.x); acc0.y = fmaf(w2, v2.y, acc0.y);
            acc0.z = fmaf(w2, v2.z, acc0.z); acc0.w = fmaf(w2, v2.w, acc0.w);
            acc1.x = fmaf(w3, v3.x, acc1.x); acc1.y = fmaf(w3, v3.y, acc1.y);
            acc1.z = fmaf(w3, v3.z, acc1.z); acc1.w = fmaf(w3, v3.w, acc1.w);
        }
    }
    acc0.x += acc1.x; acc0.y += acc1.y; acc0.z += acc1.z; acc0.w += acc1.w;
    acc0.x += __shfl_xor_sync(0xffffffffu, acc0.x, 16);
    acc0.y += __shfl_xor_sync(0xffffffffu, acc0.y, 16);
    acc0.z += __shfl_xor_sync(0xffffffffu, acc0.z, 16);
    acc0.w += __shfl_xor_sync(0xffffffffu, acc0.w, 16);
    if (lane < 16) {
        const float dn = g_deg[n];
        const float d2 = dn * dn;
        const float4 self = h[(long long)n * 16 + c];
        const float4 bb = ((const float4*)bias)[c];
        float4 o;
        o.x = bb.x + dn * acc0.x + d2 * self.x;
        o.y = bb.y + dn * acc0.y + d2 * self.y;
        o.z = bb.z + dn * acc0.z + d2 * self.z;
        o.w = bb.w + dn * acc0.w + d2 * self.w;
        out[(long long)n * 16 + c] = o;
    }
}

// ---------------- launch -----------------------------------------------------
extern "C" void kernel_launch(void* const* d_in, const int* in_sizes, int n_in,
                              void* d_out, int out_size) {
    const float*  x    = (const float*)d_in[0];
    const void*   ei   = d_in[1];
    const float4* eatt = (const float4*)d_in[2];
    const float*  w1   = (const float*)d_in[3];
    const float*  b1   = (const float*)d_in[4];
    const float*  w2   = (const float*)d_in[5];
    const float*  b2   = (const float*)d_in[6];
    float* out = (float*)d_out;

    constexpr int T = 256;
    const int smem1 = (160 * 128 + 64 * 160) * 4;  // 122880 B
    const int smem2 = (160 * 64 + 64 * 160) * 4;   //  81920 B
    cudaFuncSetAttribute(gemm_kernel<HID, FN, false>,
                         cudaFuncAttributeMaxDynamicSharedMemorySize, smem1);
    cudaFuncSetAttribute(gemm_kernel<OUTC, HID, true>,
                         cudaFuncAttributeMaxDynamicSharedMemorySize, smem2);

    detect_zero_kernel<<<(PADN + T - 1) / T, T>>>(ei);    // 1
    hist_kernel<<<(EE + T - 1) / T, T>>>(ei);             // 2
    scan_kernel<<<2, 1024>>>();                           // 3 (dinv fused)
    reorder_kernel<<<(EE + T - 1) / T, T>>>(ei);          // 4  <- profiled slot

    const unsigned wblocks = (NN * 32 + T - 1) / T;       // warp per node
    agg_gather_kernel<<<wblocks, T>>>(eatt);              // 5

    const unsigned gblocks = (NN + 63) / 64;              // 1563

    gemm_kernel<HID, FN, false><<<gblocks, T, smem1>>>(x, w1, (float*)g_h1);   // 6
    gather128_kernel<<<wblocks, T>>>(g_h1, b1, g_out1);                        // 7
    gemm_kernel<OUTC, HID, true><<<gblocks, T, smem2>>>(
        (const float*)g_out1, w2, (float*)g_h2);                               // 8
    gather64_kernel<<<wblocks, T>>>(g_h2, b2, (float4*)out);                   // 9
}

// round 6
// speedup vs baseline: 20.2626x; 11.9358x over previous
#include <cuda_runtime.h>
#include <cuda_bf16.h>

#define NN 100000
#define EE 1600000
#define FN 128
#define FE 32
#define HID 128
#define OUTC 64
#define PADN 102400   // NN padded to multiple of 4096

// ---------------- scratch (device globals; zero-initialized) -----------------
// RULE (R5 lesson): these symbols are ONLY referenced from device code.
// Passing them as kernel arguments from host code binds the host-side shadow
// object (GPU-dereferenceable via ATS on GB300 -> silent host-memory traffic).
__device__ float4 g_agg [NN * (FE/4)];     // [N,32]  aggregated edge features
__device__ float4 g_deg4[PADN/4];          // dinv (padded, vector-aligned)
__device__ float4 g_h1  [NN * (HID/4)];    // [N,128] h @ w1
__device__ float4 g_out1[NN * (HID/4)];    // [N,128] layer-1 output
__device__ float4 g_h2  [NN * (OUTC/4)];   // [N,64]  h2 @ w2
__device__ float  g_wt1[HID  * (FN + FE)]; // w1 transposed: [128][160]
__device__ float  g_wt2[OUTC * (HID + FE)];// w2 transposed: [64][160]

__device__ int4 g_cnt_row4[PADN/4];        // INVARIANT: zero at kernel_launch entry
__device__ int4 g_cnt_col4[PADN/4];        // (zero-init + cleanup_kernel at exit)
__device__ int  g_cur_row[NN];
__device__ int  g_cur_col[NN];
__device__ int4 g_base_row4[PADN/4 + 1];
__device__ int4 g_base_col4[PADN/4 + 1];
__device__ int  g_csr_row_e  [EE];  // edge ids sorted by row  (for agg gather)
__device__ int  g_csr_col_src[EE];  // src node ids sorted by col (for msg gather)

#define g_deg      ((float*)g_deg4)
#define g_cnt_row  ((int*)g_cnt_row4)
#define g_cnt_col  ((int*)g_cnt_col4)
#define g_base_row ((int*)g_base_row4)
#define g_base_col ((int*)g_base_col4)

// ---------------- helpers ---------------------------------------------------
__device__ __forceinline__ long long getidx(const void* ei, long long pos, int is64) {
    if (is64) return ((const long long*)ei)[pos];
    return (long long)((const int*)ei)[pos];
}

// int64 vs int32 detection from the first 512 bytes: if data is int32, an
// 8-byte read packs two ids and is >= 2^32 unless the hi word is 0 (p ~ 1e-5
// per entry; 64 entries => misdetection p ~ 1e-320).
__device__ __forceinline__ int detect64(const void* ei) {
    const longlong4* p = (const longlong4*)ei;
    int ok = 1;
#pragma unroll
    for (int i = 0; i < 16; ++i) {
        longlong4 v = p[i];
        ok &= (v.x >= 0 && v.x < NN) & (v.y >= 0 && v.y < NN)
            & (v.z >= 0 && v.z < NN) & (v.w >= 0 && v.w < NN);
    }
    return ok;
}

// ---------------- 1: degree histograms (counters pre-zeroed by invariant) ----
__global__ __launch_bounds__(256) void hist_kernel(const void* __restrict__ ei) {
    __shared__ int s64;
    if (threadIdx.x == 0) s64 = detect64(ei);
    __syncthreads();
    const int is64 = s64;
    long long e = (long long)blockIdx.x * blockDim.x + threadIdx.x;
    if (e >= EE) return;
    atomicAdd(&g_cnt_row[(int)getidx(ei, e, is64)], 1);
    atomicAdd(&g_cnt_col[(int)getidx(ei, EE + e, is64)], 1);
}

// ---------------- 2: exclusive scan + dinv (one block per array) ------------
__global__ __launch_bounds__(1024, 1) void scan_kernel() {
    const int4* c4 = (blockIdx.x == 0) ? g_cnt_row4 : g_cnt_col4;
    int4* b4       = (blockIdx.x == 0) ? g_base_row4 : g_base_col4;
    const int t = threadIdx.x;
    constexpr int PER4 = PADN / 4 / 1024;   // 25 int4 per thread

    int s = 0;
#pragma unroll
    for (int i = 0; i < PER4; ++i) {
        int4 q = c4[t * PER4 + i];
        s += q.x + q.y + q.z + q.w;
    }
    __shared__ int sm[1024];
    sm[t] = s;
    __syncthreads();
    for (int off = 1; off < 1024; off <<= 1) {
        int u = (t >= off) ? sm[t - off] : 0;
        __syncthreads();
        sm[t] += u;
        __syncthreads();
    }
    int run = sm[t] - s;   // exclusive prefix
#pragma unroll
    for (int i = 0; i < PER4; ++i) {
        int4 q = c4[t * PER4 + i];
        int4 b;
        b.x = run;
        b.y = b.x + q.x;
        b.z = b.y + q.y;
        b.w = b.z + q.z;
        run = b.w + q.w;
        b4[t * PER4 + i] = b;
    }
    if (blockIdx.x == 1) {   // dinv = rsqrt(in_degree + 1), fused
#pragma unroll
        for (int i = 0; i < PER4; ++i) {
            int4 q = c4[t * PER4 + i];
            float4 d;
            d.x = rsqrtf((float)(q.x + 1));
            d.y = rsqrtf((float)(q.y + 1));
            d.z = rsqrtf((float)(q.z + 1));
            d.w = rsqrtf((float)(q.w + 1));
            g_deg4[t * PER4 + i] = d;
        }
    }
}

// ---------------- 3: build both CSRs (cursors pre-zeroed by invariant) -------
__global__ __launch_bounds__(256) void reorder_kernel(const void* __restrict__ ei) {
    __shared__ int s64;
    if (threadIdx.x == 0) s64 = detect64(ei);
    __syncthreads();
    const int is64 = s64;
    long long e = (long long)blockIdx.x * blockDim.x + threadIdx.x;
    if (e >= EE) return;
    const int r = (int)getidx(ei, e, is64);
    const int c = (int)getidx(ei, EE + e, is64);
    int p = atomicAdd(&g_cur_row[r], 1);
    g_csr_row_e[g_base_row[r] + p] = (int)e;
    int q = atomicAdd(&g_cur_col[c], 1);
    g_csr_col_src[g_base_col[c] + q] = r;
}

// ---------------- 4 (PROFILED): agg[n] = sum edge_attr over row==n -----------
// warp per node: lanes split 8 float4-cols x 4 edge groups; 4-wide unroll
__global__ __launch_bounds__(256) void agg_gather_kernel(const float4* __restrict__ eattr) {
    const int warp = (blockIdx.x * blockDim.x + threadIdx.x) >> 5;
    if (warp >= NN) return;
    const int lane = threadIdx.x & 31;
    const int c = lane & 7;
    const int g = lane >> 3;
    const int beg = g_base_row[warp], end = g_base_row[warp + 1];
    float4 a0 = make_float4(0.f, 0.f, 0.f, 0.f);
    float4 a1 = make_float4(0.f, 0.f, 0.f, 0.f);
    int i = beg + g;
    for (; i + 12 < end; i += 16) {
        const int e0 = g_csr_row_e[i];
        const int e1 = g_csr_row_e[i + 4];
        const int e2 = g_csr_row_e[i + 8];
        const int e3 = g_csr_row_e[i + 12];
        const float4 v0 = eattr[(long long)e0 * 8 + c];
        const float4 v1 = eattr[(long long)e1 * 8 + c];
        const float4 v2 = eattr[(long long)e2 * 8 + c];
        const float4 v3 = eattr[(long long)e3 * 8 + c];
        a0.x += v0.x; a0.y += v0.y; a0.z += v0.z; a0.w += v0.w;
        a1.x += v1.x; a1.y += v1.y; a1.z += v1.z; a1.w += v1.w;
        a0.x += v2.x; a0.y += v2.y; a0.z += v2.z; a0.w += v2.w;
        a1.x += v3.x; a1.y += v3.y; a1.z += v3.z; a1.w += v3.w;
    }
    for (; i < end; i += 4) {
        const float4 v = eattr[(long long)g_csr_row_e[i] * 8 + c];
        a0.x += v.x; a0.y += v.y; a0.z += v.z; a0.w += v.w;
    }
    a0.x += a1.x; a0.y += a1.y; a0.z += a1.z; a0.w += a1.w;
#pragma unroll
    for (int off = 8; off <= 16; off <<= 1) {
        a0.x += __shfl_xor_sync(0xffffffffu, a0.x, off);
        a0.y += __shfl_xor_sync(0xffffffffu, a0.y, off);
        a0.z += __shfl_xor_sync(0xffffffffu, a0.z, off);
        a0.w += __shfl_xor_sync(0xffffffffu, a0.w, off);
    }
    if (lane < 8) g_agg[warp * 8 + c] = a0;
}

// ---------------- 5: transpose weights to [OC][K] -----------------------------
__global__ __launch_bounds__(256) void wtrans_kernel(const float* __restrict__ w1,
                                                     const float* __restrict__ w2) {
    int tid = blockIdx.x * blockDim.x + threadIdx.x;
    if (tid < 160 * 128) {
        int k = tid >> 7, c = tid & 127;      // coalesced read of w1[k][c]
        g_wt1[c * 160 + k] = w1[tid];
    }
    int t2 = tid - 160 * 128;
    if (t2 >= 0 && t2 < 160 * 64) {
        int k = t2 >> 6, c = t2 & 63;
        g_wt2[c * 160 + k] = w2[t2];
    }
}

// ---------------- GEMM: out[N,OC] = [A | agg] @ W ----------------------------
// 256 threads, 64-node tile; input tile in smem (40 KB -> 5 blocks/SM).
// Weights stream as per-thread contiguous LDG.128 from the transposed copy.
// All scratch buffers selected in DEVICE code (template flags), never via args.
template <int OC, int CA, bool RELU, bool SRC_OUT1>
__global__ __launch_bounds__(256) void gemm_kernel(const float* __restrict__ Aext) {
    constexpr int K = CA + FE;
    constexpr int K4 = K / 4;
    constexpr int CA4 = CA / 4;
    constexpr int TN = 64;
    constexpr int CPT = OC / 64;            // cols per thread: 2 or 1

    const float4* A4  = SRC_OUT1 ? (const float4*)g_out1 : (const float4*)Aext;
    const float4* WT4 = (OC == 128) ? (const float4*)g_wt1 : (const float4*)g_wt2;
    float*        Out = (OC == 128) ? (float*)g_h1 : (float*)g_h2;

    __shared__ float4 ins4[TN * K4];        // 40960 B
    const int tid = threadIdx.x;
    const long long nb = (long long)blockIdx.x * TN;

    for (int idx = tid; idx < TN * CA4; idx += 256) {
        int n = idx / CA4, kk = idx % CA4;
        long long node = nb + n;
        float4 v = make_float4(0.f, 0.f, 0.f, 0.f);
        if (node < NN) {
            v = A4[node * CA4 + kk];
            if (RELU) {
                v.x = fmaxf(v.x, 0.f); v.y = fmaxf(v.y, 0.f);
                v.z = fmaxf(v.z, 0.f); v.w = fmaxf(v.w, 0.f);
            }
        }
        ins4[n * K4 + kk] = v;
    }
    for (int idx = tid; idx < TN * 8; idx += 256) {
        int n = idx / 8, kk = idx % 8;
        long long node = nb + n;
        ins4[n * K4 + CA4 + kk] =
            (node < NN) ? g_agg[node * 8 + kk] : make_float4(0.f, 0.f, 0.f, 0.f);
    }
    __syncthreads();

    const int c0  = tid & 63;
    const int seg = tid >> 6;               // 4 segs x 16 nodes
    float acc[CPT][16];
#pragma unroll
    for (int p = 0; p < CPT; ++p)
#pragma unroll
        for (int n = 0; n < 16; ++n) acc[p][n] = 0.f;

    const float4* row = ins4 + (seg * 16) * K4;
#pragma unroll 2
    for (int k4 = 0; k4 < K4; ++k4) {
        float4 w[CPT];
#pragma unroll
        for (int p = 0; p < CPT; ++p) w[p] = WT4[(c0 + 64 * p) * K4 + k4];
#pragma unroll
        for (int n = 0; n < 16; ++n) {
            const float4 iv = row[n * K4 + k4];
#pragma unroll
            for (int p = 0; p < CPT; ++p) {
                float a = acc[p][n];
                a = fmaf(iv.x, w[p].x, a);
                a = fmaf(iv.y, w[p].y, a);
                a = fmaf(iv.z, w[p].z, a);
                a = fmaf(iv.w, w[p].w, a);
                acc[p][n] = a;
            }
        }
    }

#pragma unroll
    for (int n = 0; n < 16; ++n) {
        long long node = nb + seg * 16 + n;
        if (node < NN) {
#pragma unroll
            for (int p = 0; p < CPT; ++p)
                Out[node * OC + c0 + 64 * p] = acc[p][n];
        }
    }
}

// ---------------- layer gather, 128-dim: warp per node, MLP 4 ----------------
// out1[n] = b + dinv[n]*sum(dinv[s]*h1[s]) + dinv[n]^2*h1[n]
__global__ __launch_bounds__(256) void gather128_kernel(const float* __restrict__ bias) {
    const float4* h = g_h1;
    float4* out = g_out1;
    const int n = (blockIdx.x * blockDim.x + threadIdx.x) >> 5;
    if (n >= NN) return;
    const int lane = threadIdx.x & 31;
    const int beg = g_base_col[n], end = g_base_col[n + 1];
    float4 acc0 = make_float4(0.f, 0.f, 0.f, 0.f);
    float4 acc1 = make_float4(0.f, 0.f, 0.f, 0.f);
    for (int i0 = beg; i0 < end; i0 += 32) {
        const int slot = i0 + lane;
        int s = 0; float w = 0.f;
        if (slot < end) { s = g_csr_col_src[slot]; w = g_deg[s]; }
        const int m = min(32, end - i0);
        for (int j = 0; j < m; j += 4) {
            const int   s0 = __shfl_sync(0xffffffffu, s, j);
            const int   s1 = __shfl_sync(0xffffffffu, s, j + 1);
            const int   s2 = __shfl_sync(0xffffffffu, s, j + 2);
            const int   s3 = __shfl_sync(0xffffffffu, s, j + 3);
            const float w0 = __shfl_sync(0xffffffffu, w, j);
            const float w1 = __shfl_sync(0xffffffffu, w, j + 1);
            const float w2 = __shfl_sync(0xffffffffu, w, j + 2);
            const float w3 = __shfl_sync(0xffffffffu, w, j + 3);
            const float4 v0 = h[(long long)s0 * 32 + lane];
            const float4 v1 = h[(long long)s1 * 32 + lane];
            const float4 v2 = h[(long long)s2 * 32 + lane];
            const float4 v3 = h[(long long)s3 * 32 + lane];
            acc0.x = fmaf(w0, v0.x, acc0.x); acc0.y = fmaf(w0, v0.y, acc0.y);
            acc0.z = fmaf(w0, v0.z, acc0.z); acc0.w = fmaf(w0, v0.w, acc0.w);
            acc1.x = fmaf(w1, v1.x, acc1.x); acc1.y = fmaf(w1, v1.y, acc1.y);
            acc1.z = fmaf(w1, v1.z, acc1.z); acc1.w = fmaf(w1, v1.w, acc1.w);
            acc0.x = fmaf(w2, v2.x, acc0.x); acc0.y = fmaf(w2, v2.y, acc0.y);
            acc0.z = fmaf(w2, v2.z, acc0.z); acc0.w = fmaf(w2, v2.w, acc0.w);
            acc1.x = fmaf(w3, v3.x, acc1.x); acc1.y = fmaf(w3, v3.y, acc1.y);
            acc1.z = fmaf(w3, v3.z, acc1.z); acc1.w = fmaf(w3, v3.w, acc1.w);
        }
    }
    acc0.x += acc1.x; acc0.y += acc1.y; acc0.z += acc1.z; acc0.w += acc1.w;
    const float dn = g_deg[n];
    const float d2 = dn * dn;
    const float4 self = h[(long long)n * 32 + lane];
    const float4 bb = ((const float4*)bias)[lane];
    float4 o;
    o.x = bb.x + dn * acc0.x + d2 * self.x;
    o.y = bb.y + dn * acc0.y + d2 * self.y;
    o.z = bb.z + dn * acc0.z + d2 * self.z;
    o.w = bb.w + dn * acc0.w + d2 * self.w;
    out[(long long)n * 32 + lane] = o;
}

// ---------------- layer gather, 64-dim: warp per node, half-warp pairs -------
__global__ __launch_bounds__(256) void gather64_kernel(const float* __restrict__ bias,
                                                       float4* __restrict__ out) {
    const float4* h = g_h2;
    const int n = (blockIdx.x * blockDim.x + threadIdx.x) >> 5;
    if (n >= NN) return;
    const int lane = threadIdx.x & 31;
    const int c = lane & 15;
    const int g = lane >> 4;
    const int beg = g_base_col[n], end = g_base_col[n + 1];
    float4 acc0 = make_float4(0.f, 0.f, 0.f, 0.f);
    float4 acc1 = make_float4(0.f, 0.f, 0.f, 0.f);
    for (int i0 = beg; i0 < end; i0 += 32) {
        const int slot = i0 + lane;
        int s = 0; float w = 0.f;
        if (slot < end) { s = g_csr_col_src[slot]; w = g_deg[s]; }
        const int m = min(32, end - i0);
        for (int j = 0; j < m; j += 8) {
            const int   s0 = __shfl_sync(0xffffffffu, s, j + g);
            const int   s1 = __shfl_sync(0xffffffffu, s, j + 2 + g);
            const int   s2 = __shfl_sync(0xffffffffu, s, j + 4 + g);
            const int   s3 = __shfl_sync(0xffffffffu, s, j + 6 + g);
            const float w0 = __shfl_sync(0xffffffffu, w, j + g);
            const float w1 = __shfl_sync(0xffffffffu, w, j + 2 + g);
            const float w2 = __shfl_sync(0xffffffffu, w, j + 4 + g);
            const float w3 = __shfl_sync(0xffffffffu, w, j + 6 + g);
            const float4 v0 = h[(long long)s0 * 16 + c];
            const float4 v1 = h[(long long)s1 * 16 + c];
            const float4 v2 = h[(long long)s2 * 16 + c];
            const float4 v3 = h[(long long)s3 * 16 + c];
            acc0.x = fmaf(w0, v0.x, acc0.x); acc0.y = fmaf(w0, v0.y, acc0.y);
            acc0.z = fmaf(w0, v0.z, acc0.z); acc0.w = fmaf(w0, v0.w, acc0.w);
            acc1.x = fmaf(w1, v1.x, acc1.x); acc1.y = fmaf(w1, v1.y, acc1.y);
            acc1.z = fmaf(w1, v1.z, acc1.z); acc1.w = fmaf(w1, v1.w, acc1.w);
            acc0.x = fmaf(w2, v2.x, acc0.x); acc0.y = fmaf(w2, v2.y, acc0.y);
            acc0.z = fmaf(w2, v2.z, acc0.z); acc0.w = fmaf(w2, v2.w, acc0.w);
            acc1.x = fmaf(w3, v3.x, acc1.x); acc1.y = fmaf(w3, v3.y, acc1.y);
            acc1.z = fmaf(w3, v3.z, acc1.z); acc1.w = fmaf(w3, v3.w, acc1.w);
        }
    }
    acc0.x += acc1.x; acc0.y += acc1.y; acc0.z += acc1.z; acc0.w += acc1.w;
    acc0.x += __shfl_xor_sync(0xffffffffu, acc0.x, 16);
    acc0.y += __shfl_xor_sync(0xffffffffu, acc0.y, 16);
    acc0.z += __shfl_xor_sync(0xffffffffu, acc0.z, 16);
    acc0.w += __shfl_xor_sync(0xffffffffu, acc0.w, 16);
    if (lane < 16) {
        const float dn = g_deg[n];
        const float d2 = dn * dn;
        const float4 self = h[(long long)n * 16 + c];
        const float4 bb = ((const float4*)bias)[c];
        float4 o;
        o.x = bb.x + dn * acc0.x + d2 * self.x;
        o.y = bb.y + dn * acc0.y + d2 * self.y;
        o.z = bb.z + dn * acc0.z + d2 * self.z;
        o.w = bb.w + dn * acc0.w + d2 * self.w;
        out[(long long)n * 16 + c] = o;
    }
}

// ---------------- 10: restore zero-counter invariant --------------------------
__global__ __launch_bounds__(256) void cleanup_kernel() {
    int tid = blockIdx.x * blockDim.x + threadIdx.x;
    if (tid < PADN / 4) {
        g_cnt_row4[tid] = make_int4(0, 0, 0, 0);
        g_cnt_col4[tid] = make_int4(0, 0, 0, 0);
    }
    if (tid < NN) { g_cur_row[tid] = 0; g_cur_col[tid] = 0; }
}

// ---------------- launch -----------------------------------------------------
extern "C" void kernel_launch(void* const* d_in, const int* in_sizes, int n_in,
                              void* d_out, int out_size) {
    const float*  x    = (const float*)d_in[0];
    const void*   ei   = d_in[1];
    const float4* eatt = (const float4*)d_in[2];
    const float*  w1   = (const float*)d_in[3];
    const float*  b1   = (const float*)d_in[4];
    const float*  w2   = (const float*)d_in[5];
    const float*  b2   = (const float*)d_in[6];
    float* out = (float*)d_out;

    constexpr int T = 256;
    const unsigned eblocks = (EE + T - 1) / T;          // 6250
    const unsigned wblocks = (NN * 32 + T - 1) / T;     // warp per node: 12500
    const unsigned gblocks = (NN + 63) / 64;            // 1563

    hist_kernel<<<eblocks, T>>>(ei);                            // 1
    scan_kernel<<<2, 1024>>>();                                 // 2 (+dinv)
    reorder_kernel<<<eblocks, T>>>(ei);                         // 3
    agg_gather_kernel<<<wblocks, T>>>(eatt);                    // 4  <- PROFILED
    wtrans_kernel<<<120, T>>>(w1, w2);                          // 5

    gemm_kernel<HID, FN, false, false><<<gblocks, T>>>(x);      // 6: x -> g_h1
    gather128_kernel<<<wblocks, T>>>(b1);                       // 7: g_h1 -> g_out1
    gemm_kernel<OUTC, HID, true, true><<<gblocks, T>>>(x);      // 8: g_out1 -> g_h2 (arg unused)
    gather64_kernel<<<wblocks, T>>>(b2, (float4*)out);          // 9: g_h2 -> d_out

    cleanup_kernel<<<(NN + T - 1) / T, T>>>();                  // 10 (invariant)
}

// round 7
// speedup vs baseline: 20.9919x; 1.0360x over previous
#include <cuda_runtime.h>
#include <cuda_bf16.h>

#define NN 100000
#define EE 1600000
#define FN 128
#define FE 32
#define HID 128
#define OUTC 64
#define PADN 102400   // NN padded to multiple of 4096

// ---------------- scratch (device globals; zero-initialized) -----------------
// RULE (R5 lesson): these symbols are ONLY referenced from device code.
// Passing them as kernel arguments from host code binds the host-side shadow
// object (GPU-dereferenceable via ATS on GB300 -> silent host-memory traffic).
__device__ float4 g_agg [NN * (FE/4)];     // [N,32]  aggregated edge features
__device__ float4 g_deg4[PADN/4];          // dinv (padded, vector-aligned)
__device__ float4 g_h1  [NN * (HID/4)];    // [N,128] h @ w1
__device__ float4 g_out1[NN * (HID/4)];    // [N,128] layer-1 output
__device__ float4 g_h2  [NN * (OUTC/4)];   // [N,64]  h2 @ w2
__device__ float  g_wt1[HID  * (FN + FE)]; // w1 transposed: [128][160]
__device__ float  g_wt2[OUTC * (HID + FE)];// w2 transposed: [64][160]

__device__ int4 g_cnt_row4[PADN/4];        // INVARIANT: zero at kernel_launch entry
__device__ int4 g_cnt_col4[PADN/4];        // (zero-init + cleanup at pipeline end)
__device__ int  g_cur_row[NN];
__device__ int  g_cur_col[NN];
__device__ int4 g_base_row4[PADN/4 + 1];
__device__ int4 g_base_col4[PADN/4 + 1];
__device__ int  g_csr_row_e  [EE];  // edge ids sorted by row  (for agg gather)
__device__ int  g_csr_col_src[EE];  // src node ids sorted by col (for msg gather)

#define g_deg      ((float*)g_deg4)
#define g_cnt_row  ((int*)g_cnt_row4)
#define g_cnt_col  ((int*)g_cnt_col4)
#define g_base_row ((int*)g_base_row4)
#define g_base_col ((int*)g_base_col4)

// ---------------- f32x2 packed-FMA helpers (sm_103a FFMA2, PTX-only) --------
#define FMA_F32X2(d, a, b, c) \
    asm("fma.rn.f32x2 %0, %1, %2, %3;" : "=l"(d) : "l"(a), "l"(b), "l"(c))
#define BCAST_F32X2(d, f) \
    asm("mov.b64 %0, {%1, %1};" : "=l"(d) : "r"(__float_as_uint(f)))
#define UNPACK_F32X2(lo, hi, v) \
    asm("mov.b64 {%0, %1}, %2;" : "=r"(lo), "=r"(hi) : "l"(v))

__device__ __forceinline__ float f4c(const float4& v, int k) {
    return k == 0 ? v.x : (k == 1 ? v.y : (k == 2 ? v.z : v.w));
}

// ---------------- helpers ---------------------------------------------------
__device__ __forceinline__ long long getidx(const void* ei, long long pos, int is64) {
    if (is64) return ((const long long*)ei)[pos];
    return (long long)((const int*)ei)[pos];
}

// int64 vs int32 detection from the first 512 bytes: if data is int32, an
// 8-byte read packs two ids and is >= 2^32 unless the hi word is 0.
__device__ __forceinline__ int detect64(const void* ei) {
    const longlong4* p = (const longlong4*)ei;
    int ok = 1;
#pragma unroll
    for (int i = 0; i < 16; ++i) {
        longlong4 v = p[i];
        ok &= (v.x >= 0 && v.x < NN) & (v.y >= 0 && v.y < NN)
            & (v.z >= 0 && v.z < NN) & (v.w >= 0 && v.w < NN);
    }
    return ok;
}

// ---------------- 1: degree histograms + weight transpose (fused) ------------
#define EBLOCKS ((EE + 255) / 256)   // 6250
__global__ __launch_bounds__(256) void hist_kernel(const void* __restrict__ ei,
                                                   const float* __restrict__ w1,
                                                   const float* __restrict__ w2) {
    if (blockIdx.x >= EBLOCKS) {   // weight-transpose tail blocks
        int tid = (blockIdx.x - EBLOCKS) * 256 + threadIdx.x;
        if (tid < 160 * 128) {
            int k = tid >> 7, c = tid & 127;
            g_wt1[c * 160 + k] = w1[tid];
        }
        int t2 = tid - 160 * 128;
        if (t2 >= 0 && t2 < 160 * 64) {
            int k = t2 >> 6, c = t2 & 63;
            g_wt2[c * 160 + k] = w2[t2];
        }
        return;
    }
    __shared__ int s64;
    if (threadIdx.x == 0) s64 = detect64(ei);
    __syncthreads();
    const int is64 = s64;
    long long e = (long long)blockIdx.x * blockDim.x + threadIdx.x;
    if (e >= EE) return;
    atomicAdd(&g_cnt_row[(int)getidx(ei, e, is64)], 1);
    atomicAdd(&g_cnt_col[(int)getidx(ei, EE + e, is64)], 1);
}

// ---------------- 2: exclusive scan + dinv (one block per array) ------------
__global__ __launch_bounds__(1024, 1) void scan_kernel() {
    const int4* c4 = (blockIdx.x == 0) ? g_cnt_row4 : g_cnt_col4;
    int4* b4       = (blockIdx.x == 0) ? g_base_row4 : g_base_col4;
    const int t = threadIdx.x;
    constexpr int PER4 = PADN / 4 / 1024;   // 25 int4 per thread

    int s = 0;
#pragma unroll
    for (int i = 0; i < PER4; ++i) {
        int4 q = c4[t * PER4 + i];
        s += q.x + q.y + q.z + q.w;
    }
    __shared__ int sm[1024];
    sm[t] = s;
    __syncthreads();
    for (int off = 1; off < 1024; off <<= 1) {
        int u = (t >= off) ? sm[t - off] : 0;
        __syncthreads();
        sm[t] += u;
        __syncthreads();
    }
    int run = sm[t] - s;   // exclusive prefix
#pragma unroll
    for (int i = 0; i < PER4; ++i) {
        int4 q = c4[t * PER4 + i];
        int4 b;
        b.x = run;
        b.y = b.x + q.x;
        b.z = b.y + q.y;
        b.w = b.z + q.z;
        run = b.w + q.w;
        b4[t * PER4 + i] = b;
    }
    if (blockIdx.x == 1) {   // dinv = rsqrt(in_degree + 1), fused
#pragma unroll
        for (int i = 0; i < PER4; ++i) {
            int4 q = c4[t * PER4 + i];
            float4 d;
            d.x = rsqrtf((float)(q.x + 1));
            d.y = rsqrtf((float)(q.y + 1));
            d.z = rsqrtf((float)(q.z + 1));
            d.w = rsqrtf((float)(q.w + 1));
            g_deg4[t * PER4 + i] = d;
        }
    }
}

// ---------------- 3: build both CSRs (cursors pre-zeroed by invariant) -------
__global__ __launch_bounds__(256) void reorder_kernel(const void* __restrict__ ei) {
    __shared__ int s64;
    if (threadIdx.x == 0) s64 = detect64(ei);
    __syncthreads();
    const int is64 = s64;
    long long e = (long long)blockIdx.x * blockDim.x + threadIdx.x;
    if (e >= EE) return;
    const int r = (int)getidx(ei, e, is64);
    const int c = (int)getidx(ei, EE + e, is64);
    int p = atomicAdd(&g_cur_row[r], 1);
    g_csr_row_e[g_base_row[r] + p] = (int)e;
    int q = atomicAdd(&g_cur_col[c], 1);
    g_csr_col_src[g_base_col[c] + q] = r;
}

// ---------------- 4 (PROFILED): agg[n] = sum edge_attr over row==n -----------
__global__ __launch_bounds__(256) void agg_gather_kernel(const float4* __restrict__ eattr) {
    const int warp = (blockIdx.x * blockDim.x + threadIdx.x) >> 5;
    if (warp >= NN) return;
    const int lane = threadIdx.x & 31;
    const int c = lane & 7;
    const int g = lane >> 3;
    const int beg = g_base_row[warp], end = g_base_row[warp + 1];
    float4 a0 = make_float4(0.f, 0.f, 0.f, 0.f);
    float4 a1 = make_float4(0.f, 0.f, 0.f, 0.f);
    int i = beg + g;
    for (; i + 12 < end; i += 16) {
        const int e0 = g_csr_row_e[i];
        const int e1 = g_csr_row_e[i + 4];
        const int e2 = g_csr_row_e[i + 8];
        const int e3 = g_csr_row_e[i + 12];
        const float4 v0 = eattr[(long long)e0 * 8 + c];
        const float4 v1 = eattr[(long long)e1 * 8 + c];
        const float4 v2 = eattr[(long long)e2 * 8 + c];
        const float4 v3 = eattr[(long long)e3 * 8 + c];
        a0.x += v0.x; a0.y += v0.y; a0.z += v0.z; a0.w += v0.w;
        a1.x += v1.x; a1.y += v1.y; a1.z += v1.z; a1.w += v1.w;
        a0.x += v2.x; a0.y += v2.y; a0.z += v2.z; a0.w += v2.w;
        a1.x += v3.x; a1.y += v3.y; a1.z += v3.z; a1.w += v3.w;
    }
    for (; i < end; i += 4) {
        const float4 v = eattr[(long long)g_csr_row_e[i] * 8 + c];
        a0.x += v.x; a0.y += v.y; a0.z += v.z; a0.w += v.w;
    }
    a0.x += a1.x; a0.y += a1.y; a0.z += a1.z; a0.w += a1.w;
#pragma unroll
    for (int off = 8; off <= 16; off <<= 1) {
        a0.x += __shfl_xor_sync(0xffffffffu, a0.x, off);
        a0.y += __shfl_xor_sync(0xffffffffu, a0.y, off);
        a0.z += __shfl_xor_sync(0xffffffffu, a0.z, off);
        a0.w += __shfl_xor_sync(0xffffffffu, a0.w, off);
    }
    if (lane < 8) g_agg[warp * 8 + c] = a0;
}

// ---------------- GEMM (f32x2): out[N,OC] = [A | agg] @ W --------------------
// 256 threads, 64-node tile. Input tile staged K-MAJOR in smem: smk[k][n], so
// one LDS.128 yields 4 consecutive nodes' values at fixed k = 2 f32x2 operands.
// Weights broadcast-packed per (k, col); FFMA2 halves FMA instruction count.
template <int OC, int CA, bool RELU, bool SRC_OUT1>
__global__ __launch_bounds__(256) void gemm_kernel(const float* __restrict__ Aext) {
    constexpr int K = CA + FE;              // 160
    constexpr int K4 = K / 4;               // 40
    constexpr int CA4 = CA / 4;
    constexpr int TN = 64;
    constexpr int CPT = OC / 64;            // cols per thread: 2 or 1

    const float4* A4  = SRC_OUT1 ? (const float4*)g_out1 : (const float4*)Aext;
    const float4* WT4 = (OC == 128) ? (const float4*)g_wt1 : (const float4*)g_wt2;
    float*        Out = (OC == 128) ? (float*)g_h1 : (float*)g_h2;

    __shared__ float smk[K * TN];           // [k][n], 40960 B
    const int tid = threadIdx.x;
    const long long nb = (long long)blockIdx.x * TN;

    // stage main input: consecutive threads -> consecutive n (conflict-free STS)
    for (int idx = tid; idx < TN * CA4; idx += 256) {
        const int n = idx & 63, kk = idx >> 6;       // kk in [0, CA4)
        const long long node = nb + n;
        float4 v = make_float4(0.f, 0.f, 0.f, 0.f);
        if (node < NN) {
            v = A4[node * CA4 + kk];
            if (RELU) {
                v.x = fmaxf(v.x, 0.f); v.y = fmaxf(v.y, 0.f);
                v.z = fmaxf(v.z, 0.f); v.w = fmaxf(v.w, 0.f);
            }
        }
        smk[(4 * kk + 0) * TN + n] = v.x;
        smk[(4 * kk + 1) * TN + n] = v.y;
        smk[(4 * kk + 2) * TN + n] = v.z;
        smk[(4 * kk + 3) * TN + n] = v.w;
    }
    // stage agg columns
    for (int idx = tid; idx < TN * 8; idx += 256) {
        const int n = idx & 63, kk = idx >> 6;       // kk in [0, 8)
        const long long node = nb + n;
        float4 v = (node < NN) ? g_agg[node * 8 + kk]
                               : make_float4(0.f, 0.f, 0.f, 0.f);
        smk[(CA + 4 * kk + 0) * TN + n] = v.x;
        smk[(CA + 4 * kk + 1) * TN + n] = v.y;
        smk[(CA + 4 * kk + 2) * TN + n] = v.z;
        smk[(CA + 4 * kk + 3) * TN + n] = v.w;
    }
    __syncthreads();

    const int c0  = tid & 63;
    const int seg = tid >> 6;               // 4 segs x 16 nodes
    unsigned long long acc[CPT][8];         // 8 f32x2 = 16 nodes per col
#pragma unroll
    for (int p = 0; p < CPT; ++p)
#pragma unroll
        for (int q = 0; q < 8; ++q) acc[p][q] = 0ull;   // (0.0f, 0.0f)

    const float* base = smk + seg * 16;
#pragma unroll 2
    for (int k4 = 0; k4 < K4; ++k4) {
        float4 wv[CPT];
#pragma unroll
        for (int p = 0; p < CPT; ++p) wv[p] = WT4[(c0 + 64 * p) * K4 + k4];
#pragma unroll
        for (int kk = 0; kk < 4; ++kk) {
            const longlong2* rk = (const longlong2*)(base + (4 * k4 + kk) * TN);
            const longlong2 q0 = rk[0];     // nodes 0-3  (2 f32x2)
            const longlong2 q1 = rk[1];     // nodes 4-7
            const longlong2 q2 = rk[2];     // nodes 8-11
            const longlong2 q3 = rk[3];     // nodes 12-15
#pragma unroll
            for (int p = 0; p < CPT; ++p) {
                unsigned long long wp;
                BCAST_F32X2(wp, f4c(wv[p], kk));
                FMA_F32X2(acc[p][0], (unsigned long long)q0.x, wp, acc[p][0]);
                FMA_F32X2(acc[p][1], (unsigned long long)q0.y, wp, acc[p][1]);
                FMA_F32X2(acc[p][2], (unsigned long long)q1.x, wp, acc[p][2]);
                FMA_F32X2(acc[p][3], (unsigned long long)q1.y, wp, acc[p][3]);
                FMA_F32X2(acc[p][4], (unsigned long long)q2.x, wp, acc[p][4]);
                FMA_F32X2(acc[p][5], (unsigned long long)q2.y, wp, acc[p][5]);
                FMA_F32X2(acc[p][6], (unsigned long long)q3.x, wp, acc[p][6]);
                FMA_F32X2(acc[p][7], (unsigned long long)q3.y, wp, acc[p][7]);
            }
        }
    }

#pragma unroll
    for (int q = 0; q < 8; ++q) {
        const long long n0 = nb + seg * 16 + 2 * q;
#pragma unroll
        for (int p = 0; p < CPT; ++p) {
            unsigned int lo, hi;
            UNPACK_F32X2(lo, hi, acc[p][q]);
            if (n0 < NN)     Out[n0 * OC + c0 + 64 * p]       = __uint_as_float(lo);
            if (n0 + 1 < NN) Out[(n0 + 1) * OC + c0 + 64 * p] = __uint_as_float(hi);
        }
    }
}

// ---------------- layer gather, 128-dim: warp per node, MLP 4 ----------------
// out1[n] = b + dinv[n]*sum(dinv[s]*h1[s]) + dinv[n]^2*h1[n]
__global__ __launch_bounds__(256) void gather128_kernel(const float* __restrict__ bias) {
    const float4* h = g_h1;
    float4* out = g_out1;
    const int n = (blockIdx.x * blockDim.x + threadIdx.x) >> 5;
    if (n >= NN) return;
    const int lane = threadIdx.x & 31;
    const int beg = g_base_col[n], end = g_base_col[n + 1];
    float4 acc0 = make_float4(0.f, 0.f, 0.f, 0.f);
    float4 acc1 = make_float4(0.f, 0.f, 0.f, 0.f);
    for (int i0 = beg; i0 < end; i0 += 32) {
        const int slot = i0 + lane;
        int s = 0; float w = 0.f;
        if (slot < end) { s = g_csr_col_src[slot]; w = g_deg[s]; }
        const int m = min(32, end - i0);
        for (int j = 0; j < m; j += 4) {
            const int   s0 = __shfl_sync(0xffffffffu, s, j);
            const int   s1 = __shfl_sync(0xffffffffu, s, j + 1);
            const int   s2 = __shfl_sync(0xffffffffu, s, j + 2);
            const int   s3 = __shfl_sync(0xffffffffu, s, j + 3);
            const float w0 = __shfl_sync(0xffffffffu, w, j);
            const float w1 = __shfl_sync(0xffffffffu, w, j + 1);
            const float w2 = __shfl_sync(0xffffffffu, w, j + 2);
            const float w3 = __shfl_sync(0xffffffffu, w, j + 3);
            const float4 v0 = h[(long long)s0 * 32 + lane];
            const float4 v1 = h[(long long)s1 * 32 + lane];
            const float4 v2 = h[(long long)s2 * 32 + lane];
            const float4 v3 = h[(long long)s3 * 32 + lane];
            acc0.x = fmaf(w0, v0.x, acc0.x); acc0.y = fmaf(w0, v0.y, acc0.y);
            acc0.z = fmaf(w0, v0.z, acc0.z); acc0.w = fmaf(w0, v0.w, acc0.w);
            acc1.x = fmaf(w1, v1.x, acc1.x); acc1.y = fmaf(w1, v1.y, acc1.y);
            acc1.z = fmaf(w1, v1.z, acc1.z); acc1.w = fmaf(w1, v1.w, acc1.w);
            acc0.x = fmaf(w2, v2.x, acc0.x); acc0.y = fmaf(w2, v2.y, acc0.y);
            acc0.z = fmaf(w2, v2.z, acc0.z); acc0.w = fmaf(w2, v2.w, acc0.w);
            acc1.x = fmaf(w3, v3.x, acc1.x); acc1.y = fmaf(w3, v3.y, acc1.y);
            acc1.z = fmaf(w3, v3.z, acc1.z); acc1.w = fmaf(w3, v3.w, acc1.w);
        }
    }
    acc0.x += acc1.x; acc0.y += acc1.y; acc0.z += acc1.z; acc0.w += acc1.w;
    const float dn = g_deg[n];
    const float d2 = dn * dn;
    const float4 self = h[(long long)n * 32 + lane];
    const float4 bb = ((const float4*)bias)[lane];
    float4 o;
    o.x = bb.x + dn * acc0.x + d2 * self.x;
    o.y = bb.y + dn * acc0.y + d2 * self.y;
    o.z = bb.z + dn * acc0.z + d2 * self.z;
    o.w = bb.w + dn * acc0.w + d2 * self.w;
    out[(long long)n * 32 + lane] = o;
}

// ---------------- layer gather, 64-dim + cleanup tail blocks -----------------
#define WBLOCKS ((NN * 32 + 255) / 256)   // 12500
__global__ __launch_bounds__(256) void gather64_kernel(const float* __restrict__ bias,
                                                       float4* __restrict__ out) {
    if (blockIdx.x >= WBLOCKS) {   // cleanup: restore zero-counter invariant
        int tid = (blockIdx.x - WBLOCKS) * 256 + threadIdx.x;
        if (tid < PADN / 4) {
            g_cnt_row4[tid] = make_int4(0, 0, 0, 0);
            g_cnt_col4[tid] = make_int4(0, 0, 0, 0);
        }
        if (tid < NN) { g_cur_row[tid] = 0; g_cur_col[tid] = 0; }
        return;
    }
    const float4* h = g_h2;
    const int n = (blockIdx.x * blockDim.x + threadIdx.x) >> 5;
    if (n >= NN) return;
    const int lane = threadIdx.x & 31;
    const int c = lane & 15;
    const int g = lane >> 4;
    const int beg = g_base_col[n], end = g_base_col[n + 1];
    float4 acc0 = make_float4(0.f, 0.f, 0.f, 0.f);
    float4 acc1 = make_float4(0.f, 0.f, 0.f, 0.f);
    for (int i0 = beg; i0 < end; i0 += 32) {
        const int slot = i0 + lane;
        int s = 0; float w = 0.f;
        if (slot < end) { s = g_csr_col_src[slot]; w = g_deg[s]; }
        const int m = min(32, end - i0);
        for (int j = 0; j < m; j += 8) {
            const int   s0 = __shfl_sync(0xffffffffu, s, j + g);
            const int   s1 = __shfl_sync(0xffffffffu, s, j + 2 + g);
            const int   s2 = __shfl_sync(0xffffffffu, s, j + 4 + g);
            const int   s3 = __shfl_sync(0xffffffffu, s, j + 6 + g);
            const float w0 = __shfl_sync(0xffffffffu, w, j + g);
            const float w1 = __shfl_sync(0xffffffffu, w, j + 2 + g);
            const float w2 = __shfl_sync(0xffffffffu, w, j + 4 + g);
            const float w3 = __shfl_sync(0xffffffffu, w, j + 6 + g);
            const float4 v0 = h[(long long)s0 * 16 + c];
            const float4 v1 = h[(long long)s1 * 16 + c];
            const float4 v2 = h[(long long)s2 * 16 + c];
            const float4 v3 = h[(long long)s3 * 16 + c];
            acc0.x = fmaf(w0, v0.x, acc0.x); acc0.y = fmaf(w0, v0.y, acc0.y);
            acc0.z = fmaf(w0, v0.z, acc0.z); acc0.w = fmaf(w0, v0.w, acc0.w);
            acc1.x = fmaf(w1, v1.x, acc1.x); acc1.y = fmaf(w1, v1.y, acc1.y);
            acc1.z = fmaf(w1, v1.z, acc1.z); acc1.w = fmaf(w1, v1.w, acc1.w);
            acc0.x = fmaf(w2, v2.x, acc0.x); acc0.y = fmaf(w2, v2.y, acc0.y);
            acc0.z = fmaf(w2, v2.z, acc0.z); acc0.w = fmaf(w2, v2.w, acc0.w);
            acc1.x = fmaf(w3, v3.x, acc1.x); acc1.y = fmaf(w3, v3.y, acc1.y);
            acc1.z = fmaf(w3, v3.z, acc1.z); acc1.w = fmaf(w3, v3.w, acc1.w);
        }
    }
    acc0.x += acc1.x; acc0.y += acc1.y; acc0.z += acc1.z; acc0.w += acc1.w;
    acc0.x += __shfl_xor_sync(0xffffffffu, acc0.x, 16);
    acc0.y += __shfl_xor_sync(0xffffffffu, acc0.y, 16);
    acc0.z += __shfl_xor_sync(0xffffffffu, acc0.z, 16);
    acc0.w += __shfl_xor_sync(0xffffffffu, acc0.w, 16);
    if (lane < 16) {
        const float dn = g_deg[n];
        const float d2 = dn * dn;
        const float4 self = h[(long long)n * 16 + c];
        const float4 bb = ((const float4*)bias)[c];
        float4 o;
        o.x = bb.x + dn * acc0.x + d2 * self.x;
        o.y = bb.y + dn * acc0.y + d2 * self.y;
        o.z = bb.z + dn * acc0.z + d2 * self.z;
        o.w = bb.w + dn * acc0.w + d2 * self.w;
        out[(long long)n * 16 + c] = o;
    }
}

// ---------------- launch -----------------------------------------------------
extern "C" void kernel_launch(void* const* d_in, const int* in_sizes, int n_in,
                              void* d_out, int out_size) {
    const float*  x    = (const float*)d_in[0];
    const void*   ei   = d_in[1];
    const float4* eatt = (const float4*)d_in[2];
    const float*  w1   = (const float*)d_in[3];
    const float*  b1   = (const float*)d_in[4];
    const float*  w2   = (const float*)d_in[5];
    const float*  b2   = (const float*)d_in[6];
    float* out = (float*)d_out;

    constexpr int T = 256;
    const unsigned gblocks = (NN + 63) / 64;            // 1563
    const unsigned cleanb  = (NN + T - 1) / T;          // 391

    hist_kernel<<<EBLOCKS + 120, T>>>(ei, w1, w2);              // 1 (+wtrans)
    scan_kernel<<<2, 1024>>>();                                 // 2 (+dinv)
    reorder_kernel<<<EBLOCKS, T>>>(ei);                         // 3
    agg_gather_kernel<<<WBLOCKS, T>>>(eatt);                    // 4  <- PROFILED

    gemm_kernel<HID, FN, false, false><<<gblocks, T>>>(x);      // 5: x -> g_h1
    gather128_kernel<<<WBLOCKS, T>>>(b1);                       // 6: g_h1 -> g_out1
    gemm_kernel<OUTC, HID, true, true><<<gblocks, T>>>(x);      // 7: g_out1 -> g_h2
    gather64_kernel<<<WBLOCKS + cleanb, T>>>(b2, (float4*)out); // 8 (+cleanup)
}

// round 8
// speedup vs baseline: 26.5424x; 1.2644x over previous
#include <cuda_runtime.h>
#include <cuda_bf16.h>

#define NN 100000
#define EE 1600000
#define FN 128
#define FE 32
#define HID 128
#define OUTC 64
#define PADN 102400   // NN padded to multiple of 4096
#define K4N 40        // (160 / 4) k4 groups

// ---------------- scratch (device globals; zero-initialized) -----------------
// RULE (R5 lesson): these symbols are ONLY referenced from device code.
// Passing them as kernel arguments from host code binds the host-side shadow
// object (GPU-dereferenceable via ATS on GB300 -> silent host-memory traffic).
__device__ float4 g_agg [NN * (FE/4)];     // [N,32]  aggregated edge features
__device__ float4 g_deg4[PADN/4];          // dinv (padded, vector-aligned)
__device__ float4 g_h1  [NN * (HID/4)];    // [N,128] h @ w1
__device__ float4 g_out1[NN * (HID/4)];    // [N,128] layer-1 output
__device__ float4 g_h2  [NN * (OUTC/4)];   // [N,64]  h2 @ w2
// k4-major packed weights: wt[k4][c] = (w[4k4][c], w[4k4+1][c], w[4k4+2][c], w[4k4+3][c])
// -> warp reads 32 CONSECUTIVE float4 per (k4, col-group): 4 lines, not 32.
__device__ float4 g_wt1[K4N * HID];        // [40][128]
__device__ float4 g_wt2[K4N * OUTC];       // [40][64]

__device__ int4 g_cnt_row4[PADN/4];        // INVARIANT: zero at kernel_launch entry
__device__ int4 g_cnt_col4[PADN/4];        // (zero-init + cleanup at pipeline end)
__device__ int  g_cur_row[NN];
__device__ int  g_cur_col[NN];
__device__ int4 g_base_row4[PADN/4 + 1];
__device__ int4 g_base_col4[PADN/4 + 1];
__device__ int  g_csr_row_e  [EE];  // edge ids sorted by row  (for agg gather)
__device__ int  g_csr_col_src[EE];  // src node ids sorted by col (for msg gather)

#define g_deg      ((float*)g_deg4)
#define g_cnt_row  ((int*)g_cnt_row4)
#define g_cnt_col  ((int*)g_cnt_col4)
#define g_base_row ((int*)g_base_row4)
#define g_base_col ((int*)g_base_col4)

// ---------------- f32x2 packed-FMA helpers (sm_103a FFMA2, PTX-only) --------
#define FMA_F32X2(d, a, b, c) \
    asm("fma.rn.f32x2 %0, %1, %2, %3;" : "=l"(d) : "l"(a), "l"(b), "l"(c))
#define BCAST_F32X2(d, f) \
    asm("mov.b64 %0, {%1, %1};" : "=l"(d) : "r"(__float_as_uint(f)))
#define UNPACK_F32X2(lo, hi, v) \
    asm("mov.b64 {%0, %1}, %2;" : "=r"(lo), "=r"(hi) : "l"(v))

__device__ __forceinline__ float f4c(const float4& v, int k) {
    return k == 0 ? v.x : (k == 1 ? v.y : (k == 2 ? v.z : v.w));
}

// ---------------- helpers ---------------------------------------------------
__device__ __forceinline__ long long getidx(const void* ei, long long pos, int is64) {
    if (is64) return ((const long long*)ei)[pos];
    return (long long)((const int*)ei)[pos];
}

// int64 vs int32 detection from the first 512 bytes: if data is int32, an
// 8-byte read packs two ids and is >= 2^32 unless the hi word is 0.
__device__ __forceinline__ int detect64(const void* ei) {
    const longlong4* p = (const longlong4*)ei;
    int ok = 1;
#pragma unroll
    for (int i = 0; i < 16; ++i) {
        longlong4 v = p[i];
        ok &= (v.x >= 0 && v.x < NN) & (v.y >= 0 && v.y < NN)
            & (v.z >= 0 && v.z < NN) & (v.w >= 0 && v.w < NN);
    }
    return ok;
}

// ---------------- 1: degree histograms + weight repack (fused) ---------------
#define EBLOCKS ((EE + 255) / 256)   // 6250
#define WTTHREADS (K4N * HID + K4N * OUTC)   // 5120 + 2560 = 7680
#define WTBLOCKS ((WTTHREADS + 255) / 256)   // 30
__global__ __launch_bounds__(256) void hist_kernel(const void* __restrict__ ei,
                                                   const float* __restrict__ w1,
                                                   const float* __restrict__ w2) {
    if (blockIdx.x >= EBLOCKS) {   // weight-repack tail blocks
        int tid = (blockIdx.x - EBLOCKS) * 256 + threadIdx.x;
        if (tid < K4N * HID) {
            int k4 = tid >> 7, c = tid & 127;
            float4 v;
            v.x = w1[(4 * k4 + 0) * HID + c];
            v.y = w1[(4 * k4 + 1) * HID + c];
            v.z = w1[(4 * k4 + 2) * HID + c];
            v.w = w1[(4 * k4 + 3) * HID + c];
            g_wt1[k4 * HID + c] = v;
        }
        int t2 = tid - K4N * HID;
        if (t2 >= 0 && t2 < K4N * OUTC) {
            int k4 = t2 >> 6, c = t2 & 63;
            float4 v;
            v.x = w2[(4 * k4 + 0) * OUTC + c];
            v.y = w2[(4 * k4 + 1) * OUTC + c];
            v.z = w2[(4 * k4 + 2) * OUTC + c];
            v.w = w2[(4 * k4 + 3) * OUTC + c];
            g_wt2[k4 * OUTC + c] = v;
        }
        return;
    }
    __shared__ int s64;
    if (threadIdx.x == 0) s64 = detect64(ei);
    __syncthreads();
    const int is64 = s64;
    long long e = (long long)blockIdx.x * blockDim.x + threadIdx.x;
    if (e >= EE) return;
    atomicAdd(&g_cnt_row[(int)getidx(ei, e, is64)], 1);
    atomicAdd(&g_cnt_col[(int)getidx(ei, EE + e, is64)], 1);
}

// ---------------- 2: exclusive scan + dinv (one block per array) ------------
__global__ __launch_bounds__(1024, 1) void scan_kernel() {
    const int4* c4 = (blockIdx.x == 0) ? g_cnt_row4 : g_cnt_col4;
    int4* b4       = (blockIdx.x == 0) ? g_base_row4 : g_base_col4;
    const int t = threadIdx.x;
    constexpr int PER4 = PADN / 4 / 1024;   // 25 int4 per thread

    int s = 0;
#pragma unroll
    for (int i = 0; i < PER4; ++i) {
        int4 q = c4[t * PER4 + i];
        s += q.x + q.y + q.z + q.w;
    }
    __shared__ int sm[1024];
    sm[t] = s;
    __syncthreads();
    for (int off = 1; off < 1024; off <<= 1) {
        int u = (t >= off) ? sm[t - off] : 0;
        __syncthreads();
        sm[t] += u;
        __syncthreads();
    }
    int run = sm[t] - s;   // exclusive prefix
#pragma unroll
    for (int i = 0; i < PER4; ++i) {
        int4 q = c4[t * PER4 + i];
        int4 b;
        b.x = run;
        b.y = b.x + q.x;
        b.z = b.y + q.y;
        b.w = b.z + q.z;
        run = b.w + q.w;
        b4[t * PER4 + i] = b;
    }
    if (blockIdx.x == 1) {   // dinv = rsqrt(in_degree + 1), fused
#pragma unroll
        for (int i = 0; i < PER4; ++i) {
            int4 q = c4[t * PER4 + i];
            float4 d;
            d.x = rsqrtf((float)(q.x + 1));
            d.y = rsqrtf((float)(q.y + 1));
            d.z = rsqrtf((float)(q.z + 1));
            d.w = rsqrtf((float)(q.w + 1));
            g_deg4[t * PER4 + i] = d;
        }
    }
}

// ---------------- 3: build both CSRs (cursors pre-zeroed by invariant) -------
__global__ __launch_bounds__(256) void reorder_kernel(const void* __restrict__ ei) {
    __shared__ int s64;
    if (threadIdx.x == 0) s64 = detect64(ei);
    __syncthreads();
    const int is64 = s64;
    long long e = (long long)blockIdx.x * blockDim.x + threadIdx.x;
    if (e >= EE) return;
    const int r = (int)getidx(ei, e, is64);
    const int c = (int)getidx(ei, EE + e, is64);
    int p = atomicAdd(&g_cur_row[r], 1);
    g_csr_row_e[g_base_row[r] + p] = (int)e;
    int q = atomicAdd(&g_cur_col[c], 1);
    g_csr_col_src[g_base_col[c] + q] = r;
}

// ---------------- 4 (PROFILED, control): agg[n] = sum edge_attr, row==n ------
__global__ __launch_bounds__(256) void agg_gather_kernel(const float4* __restrict__ eattr) {
    const int warp = (blockIdx.x * blockDim.x + threadIdx.x) >> 5;
    if (warp >= NN) return;
    const int lane = threadIdx.x & 31;
    const int c = lane & 7;
    const int g = lane >> 3;
    const int beg = g_base_row[warp], end = g_base_row[warp + 1];
    float4 a0 = make_float4(0.f, 0.f, 0.f, 0.f);
    float4 a1 = make_float4(0.f, 0.f, 0.f, 0.f);
    int i = beg + g;
    for (; i + 12 < end; i += 16) {
        const int e0 = g_csr_row_e[i];
        const int e1 = g_csr_row_e[i + 4];
        const int e2 = g_csr_row_e[i + 8];
        const int e3 = g_csr_row_e[i + 12];
        const float4 v0 = eattr[(long long)e0 * 8 + c];
        const float4 v1 = eattr[(long long)e1 * 8 + c];
        const float4 v2 = eattr[(long long)e2 * 8 + c];
        const float4 v3 = eattr[(long long)e3 * 8 + c];
        a0.x += v0.x; a0.y += v0.y; a0.z += v0.z; a0.w += v0.w;
        a1.x += v1.x; a1.y += v1.y; a1.z += v1.z; a1.w += v1.w;
        a0.x += v2.x; a0.y += v2.y; a0.z += v2.z; a0.w += v2.w;
        a1.x += v3.x; a1.y += v3.y; a1.z += v3.z; a1.w += v3.w;
    }
    for (; i < end; i += 4) {
        const float4 v = eattr[(long long)g_csr_row_e[i] * 8 + c];
        a0.x += v.x; a0.y += v.y; a0.z += v.z; a0.w += v.w;
    }
    a0.x += a1.x; a0.y += a1.y; a0.z += a1.z; a0.w += a1.w;
#pragma unroll
    for (int off = 8; off <= 16; off <<= 1) {
        a0.x += __shfl_xor_sync(0xffffffffu, a0.x, off);
        a0.y += __shfl_xor_sync(0xffffffffu, a0.y, off);
        a0.z += __shfl_xor_sync(0xffffffffu, a0.z, off);
        a0.w += __shfl_xor_sync(0xffffffffu, a0.w, off);
    }
    if (lane < 8) g_agg[warp * 8 + c] = a0;
}

// ---------------- GEMM (f32x2): out[N,OC] = [A | agg] @ W --------------------
// 256 threads, 64-node tile. Input staged K-MAJOR in smem (LDS.128 broadcast).
// Weights in k4-major packed layout -> warp weight reads fully coalesced
// (32 consecutive float4 = 4 lines/instruction instead of 32).
template <int OC, int CA, bool RELU, bool SRC_OUT1>
__global__ __launch_bounds__(256) void gemm_kernel(const float* __restrict__ Aext) {
    constexpr int K = CA + FE;              // 160
    constexpr int K4 = K / 4;               // 40
    constexpr int CA4 = CA / 4;
    constexpr int TN = 64;
    constexpr int CPT = OC / 64;            // cols per thread: 2 or 1

    const float4* A4  = SRC_OUT1 ? (const float4*)g_out1 : (const float4*)Aext;
    const float4* WT4 = (OC == 128) ? g_wt1 : g_wt2;
    float*        Out = (OC == 128) ? (float*)g_h1 : (float*)g_h2;

    __shared__ float smk[K * TN];           // [k][n], 40960 B
    const int tid = threadIdx.x;
    const long long nb = (long long)blockIdx.x * TN;

    // stage main input: consecutive threads -> consecutive n (conflict-free STS)
    for (int idx = tid; idx < TN * CA4; idx += 256) {
        const int n = idx & 63, kk = idx >> 6;       // kk in [0, CA4)
        const long long node = nb + n;
        float4 v = make_float4(0.f, 0.f, 0.f, 0.f);
        if (node < NN) {
            v = A4[node * CA4 + kk];
            if (RELU) {
                v.x = fmaxf(v.x, 0.f); v.y = fmaxf(v.y, 0.f);
                v.z = fmaxf(v.z, 0.f); v.w = fmaxf(v.w, 0.f);
            }
        }
        smk[(4 * kk + 0) * TN + n] = v.x;
        smk[(4 * kk + 1) * TN + n] = v.y;
        smk[(4 * kk + 2) * TN + n] = v.z;
        smk[(4 * kk + 3) * TN + n] = v.w;
    }
    // stage agg columns
    for (int idx = tid; idx < TN * 8; idx += 256) {
        const int n = idx & 63, kk = idx >> 6;       // kk in [0, 8)
        const long long node = nb + n;
        float4 v = (node < NN) ? g_agg[node * 8 + kk]
                               : make_float4(0.f, 0.f, 0.f, 0.f);
        smk[(CA + 4 * kk + 0) * TN + n] = v.x;
        smk[(CA + 4 * kk + 1) * TN + n] = v.y;
        smk[(CA + 4 * kk + 2) * TN + n] = v.z;
        smk[(CA + 4 * kk + 3) * TN + n] = v.w;
    }
    __syncthreads();

    const int c0  = tid & 63;
    const int seg = tid >> 6;               // 4 segs x 16 nodes
    unsigned long long acc[CPT][8];         // 8 f32x2 = 16 nodes per col
#pragma unroll
    for (int p = 0; p < CPT; ++p)
#pragma unroll
        for (int q = 0; q < 8; ++q) acc[p][q] = 0ull;   // (0.0f, 0.0f)

    const float* base = smk + seg * 16;
#pragma unroll 2
    for (int k4 = 0; k4 < K4; ++k4) {
        float4 wv[CPT];
#pragma unroll
        for (int p = 0; p < CPT; ++p) wv[p] = WT4[k4 * OC + c0 + 64 * p];
#pragma unroll
        for (int kk = 0; kk < 4; ++kk) {
            const longlong2* rk = (const longlong2*)(base + (4 * k4 + kk) * TN);
            const longlong2 q0 = rk[0];     // nodes 0-3  (2 f32x2)
            const longlong2 q1 = rk[1];     // nodes 4-7
            const longlong2 q2 = rk[2];     // nodes 8-11
            const longlong2 q3 = rk[3];     // nodes 12-15
#pragma unroll
            for (int p = 0; p < CPT; ++p) {
                unsigned long long wp;
                BCAST_F32X2(wp, f4c(wv[p], kk));
                FMA_F32X2(acc[p][0], (unsigned long long)q0.x, wp, acc[p][0]);
                FMA_F32X2(acc[p][1], (unsigned long long)q0.y, wp, acc[p][1]);
                FMA_F32X2(acc[p][2], (unsigned long long)q1.x, wp, acc[p][2]);
                FMA_F32X2(acc[p][3], (unsigned long long)q1.y, wp, acc[p][3]);
                FMA_F32X2(acc[p][4], (unsigned long long)q2.x, wp, acc[p][4]);
                FMA_F32X2(acc[p][5], (unsigned long long)q2.y, wp, acc[p][5]);
                FMA_F32X2(acc[p][6], (unsigned long long)q3.x, wp, acc[p][6]);
                FMA_F32X2(acc[p][7], (unsigned long long)q3.y, wp, acc[p][7]);
            }
        }
    }

#pragma unroll
    for (int q = 0; q < 8; ++q) {
        const long long n0 = nb + seg * 16 + 2 * q;
#pragma unroll
        for (int p = 0; p < CPT; ++p) {
            unsigned int lo, hi;
            UNPACK_F32X2(lo, hi, acc[p][q]);
            if (n0 < NN)     Out[n0 * OC + c0 + 64 * p]       = __uint_as_float(lo);
            if (n0 + 1 < NN) Out[(n0 + 1) * OC + c0 + 64 * p] = __uint_as_float(hi);
        }
    }
}

// ---------------- layer gather, 128-dim: warp per node, MLP 4 ----------------
// out1[n] = b + dinv[n]*sum(dinv[s]*h1[s]) + dinv[n]^2*h1[n]
__global__ __launch_bounds__(256) void gather128_kernel(const float* __restrict__ bias) {
    const float4* h = g_h1;
    float4* out = g_out1;
    const int n = (blockIdx.x * blockDim.x + threadIdx.x) >> 5;
    if (n >= NN) return;
    const int lane = threadIdx.x & 31;
    const int beg = g_base_col[n], end = g_base_col[n + 1];
    float4 acc0 = make_float4(0.f, 0.f, 0.f, 0.f);
    float4 acc1 = make_float4(0.f, 0.f, 0.f, 0.f);
    for (int i0 = beg; i0 < end; i0 += 32) {
        const int slot = i0 + lane;
        int s = 0; float w = 0.f;
        if (slot < end) { s = g_csr_col_src[slot]; w = g_deg[s]; }
        const int m = min(32, end - i0);
        for (int j = 0; j < m; j += 4) {
            const int   s0 = __shfl_sync(0xffffffffu, s, j);
            const int   s1 = __shfl_sync(0xffffffffu, s, j + 1);
            const int   s2 = __shfl_sync(0xffffffffu, s, j + 2);
            const int   s3 = __shfl_sync(0xffffffffu, s, j + 3);
            const float w0 = __shfl_sync(0xffffffffu, w, j);
            const float w1 = __shfl_sync(0xffffffffu, w, j + 1);
            const float w2 = __shfl_sync(0xffffffffu, w, j + 2);
            const float w3 = __shfl_sync(0xffffffffu, w, j + 3);
            const float4 v0 = h[(long long)s0 * 32 + lane];
            const float4 v1 = h[(long long)s1 * 32 + lane];
            const float4 v2 = h[(long long)s2 * 32 + lane];
            const float4 v3 = h[(long long)s3 * 32 + lane];
            acc0.x = fmaf(w0, v0.x, acc0.x); acc0.y = fmaf(w0, v0.y, acc0.y);
            acc0.z = fmaf(w0, v0.z, acc0.z); acc0.w = fmaf(w0, v0.w, acc0.w);
            acc1.x = fmaf(w1, v1.x, acc1.x); acc1.y = fmaf(w1, v1.y, acc1.y);
            acc1.z = fmaf(w1, v1.z, acc1.z); acc1.w = fmaf(w1, v1.w, acc1.w);
            acc0.x = fmaf(w2, v2.x, acc0.x); acc0.y = fmaf(w2, v2.y, acc0.y);
            acc0.z = fmaf(w2, v2.z, acc0.z); acc0.w = fmaf(w2, v2.w, acc0.w);
            acc1.x = fmaf(w3, v3.x, acc1.x); acc1.y = fmaf(w3, v3.y, acc1.y);
            acc1.z = fmaf(w3, v3.z, acc1.z); acc1.w = fmaf(w3, v3.w, acc1.w);
        }
    }
    acc0.x += acc1.x; acc0.y += acc1.y; acc0.z += acc1.z; acc0.w += acc1.w;
    const float dn = g_deg[n];
    const float d2 = dn * dn;
    const float4 self = h[(long long)n * 32 + lane];
    const float4 bb = ((const float4*)bias)[lane];
    float4 o;
    o.x = bb.x + dn * acc0.x + d2 * self.x;
    o.y = bb.y + dn * acc0.y + d2 * self.y;
    o.z = bb.z + dn * acc0.z + d2 * self.z;
    o.w = bb.w + dn * acc0.w + d2 * self.w;
    out[(long long)n * 32 + lane] = o;
}

// ---------------- layer gather, 64-dim + cleanup tail blocks -----------------
#define WBLOCKS ((NN * 32 + 255) / 256)   // 12500
__global__ __launch_bounds__(256) void gather64_kernel(const float* __restrict__ bias,
                                                       float4* __restrict__ out) {
    if (blockIdx.x >= WBLOCKS) {   // cleanup: restore zero-counter invariant
        int tid = (blockIdx.x - WBLOCKS) * 256 + threadIdx.x;
        if (tid < PADN / 4) {
            g_cnt_row4[tid] = make_int4(0, 0, 0, 0);
            g_cnt_col4[tid] = make_int4(0, 0, 0, 0);
        }
        if (tid < NN) { g_cur_row[tid] = 0; g_cur_col[tid] = 0; }
        return;
    }
    const float4* h = g_h2;
    const int n = (blockIdx.x * blockDim.x + threadIdx.x) >> 5;
    if (n >= NN) return;
    const int lane = threadIdx.x & 31;
    const int c = lane & 15;
    const int g = lane >> 4;
    const int beg = g_base_col[n], end = g_base_col[n + 1];
    float4 acc0 = make_float4(0.f, 0.f, 0.f, 0.f);
    float4 acc1 = make_float4(0.f, 0.f, 0.f, 0.f);
    for (int i0 = beg; i0 < end; i0 += 32) {
        const int slot = i0 + lane;
        int s = 0; float w = 0.f;
        if (slot < end) { s = g_csr_col_src[slot]; w = g_deg[s]; }
        const int m = min(32, end - i0);
        for (int j = 0; j < m; j += 8) {
            const int   s0 = __shfl_sync(0xffffffffu, s, j + g);
            const int   s1 = __shfl_sync(0xffffffffu, s, j + 2 + g);
            const int   s2 = __shfl_sync(0xffffffffu, s, j + 4 + g);
            const int   s3 = __shfl_sync(0xffffffffu, s, j + 6 + g);
            const float w0 = __shfl_sync(0xffffffffu, w, j + g);
            const float w1 = __shfl_sync(0xffffffffu, w, j + 2 + g);
            const float w2 = __shfl_sync(0xffffffffu, w, j + 4 + g);
            const float w3 = __shfl_sync(0xffffffffu, w, j + 6 + g);
            const float4 v0 = h[(long long)s0 * 16 + c];
            const float4 v1 = h[(long long)s1 * 16 + c];
            const float4 v2 = h[(long long)s2 * 16 + c];
            const float4 v3 = h[(long long)s3 * 16 + c];
            acc0.x = fmaf(w0, v0.x, acc0.x); acc0.y = fmaf(w0, v0.y, acc0.y);
            acc0.z = fmaf(w0, v0.z, acc0.z); acc0.w = fmaf(w0, v0.w, acc0.w);
            acc1.x = fmaf(w1, v1.x, acc1.x); acc1.y = fmaf(w1, v1.y, acc1.y);
            acc1.z = fmaf(w1, v1.z, acc1.z); acc1.w = fmaf(w1, v1.w, acc1.w);
            acc0.x = fmaf(w2, v2.x, acc0.x); acc0.y = fmaf(w2, v2.y, acc0.y);
            acc0.z = fmaf(w2, v2.z, acc0.z); acc0.w = fmaf(w2, v2.w, acc0.w);
            acc1.x = fmaf(w3, v3.x, acc1.x); acc1.y = fmaf(w3, v3.y, acc1.y);
            acc1.z = fmaf(w3, v3.z, acc1.z); acc1.w = fmaf(w3, v3.w, acc1.w);
        }
    }
    acc0.x += acc1.x; acc0.y += acc1.y; acc0.z += acc1.z; acc0.w += acc1.w;
    acc0.x += __shfl_xor_sync(0xffffffffu, acc0.x, 16);
    acc0.y += __shfl_xor_sync(0xffffffffu, acc0.y, 16);
    acc0.z += __shfl_xor_sync(0xffffffffu, acc0.z, 16);
    acc0.w += __shfl_xor_sync(0xffffffffu, acc0.w, 16);
    if (lane < 16) {
        const float dn = g_deg[n];
        const float d2 = dn * dn;
        const float4 self = h[(long long)n * 16 + c];
        const float4 bb = ((const float4*)bias)[c];
        float4 o;
        o.x = bb.x + dn * acc0.x + d2 * self.x;
        o.y = bb.y + dn * acc0.y + d2 * self.y;
        o.z = bb.z + dn * acc0.z + d2 * self.z;
        o.w = bb.w + dn * acc0.w + d2 * self.w;
        out[(long long)n * 16 + c] = o;
    }
}

// ---------------- launch -----------------------------------------------------
extern "C" void kernel_launch(void* const* d_in, const int* in_sizes, int n_in,
                              void* d_out, int out_size) {
    const float*  x    = (const float*)d_in[0];
    const void*   ei   = d_in[1];
    const float4* eatt = (const float4*)d_in[2];
    const float*  w1   = (const float*)d_in[3];
    const float*  b1   = (const float*)d_in[4];
    const float*  w2   = (const float*)d_in[5];
    const float*  b2   = (const float*)d_in[6];
    float* out = (float*)d_out;

    constexpr int T = 256;
    const unsigned gblocks = (NN + 63) / 64;            // 1563
    const unsigned cleanb  = (NN + T - 1) / T;          // 391

    hist_kernel<<<EBLOCKS + WTBLOCKS, T>>>(ei, w1, w2);         // 1 (+wt repack)
    scan_kernel<<<2, 1024>>>();                                 // 2 (+dinv)
    reorder_kernel<<<EBLOCKS, T>>>(ei);                         // 3
    agg_gather_kernel<<<WBLOCKS, T>>>(eatt);                    // 4  <- PROFILED

    gemm_kernel<HID, FN, false, false><<<gblocks, T>>>(x);      // 5: x -> g_h1
    gather128_kernel<<<WBLOCKS, T>>>(b1);                       // 6: g_h1 -> g_out1
    gemm_kernel<OUTC, HID, true, true><<<gblocks, T>>>(x);      // 7: g_out1 -> g_h2
    gather64_kernel<<<WBLOCKS + cleanb, T>>>(b2, (float4*)out); // 8 (+cleanup)
}

// round 9
// speedup vs baseline: 26.6474x; 1.0040x over previous
#include <cuda_runtime.h>
#include <cuda_bf16.h>

#define NN 100000
#define EE 1600000
#define FN 128
#define FE 32
#define HID 128
#define OUTC 64
#define PADN 102400   // NN padded to multiple of 4096
#define K4N 40        // (160 / 4) k4 groups

// ---------------- scratch (device globals; zero-initialized) -----------------
// RULE (R5 lesson): these symbols are ONLY referenced from device code.
// Passing them as kernel arguments from host code binds the host-side shadow
// object (GPU-dereferenceable via ATS on GB300 -> silent host-memory traffic).
__device__ float4 g_agg [NN * (FE/4)];     // [N,32]  aggregated edge features
__device__ float4 g_deg4[PADN/4];          // dinv (padded, vector-aligned)
__device__ float4 g_h1  [NN * (HID/4)];    // [N,128] h @ w1
__device__ float4 g_out1[NN * (HID/4)];    // [N,128] layer-1 output
__device__ float4 g_h2  [NN * (OUTC/4)];   // [N,64]  h2 @ w2
// k4-major packed weights: wt[k4][c] = (w[4k4..4k4+3][c]) -> coalesced streams
__device__ float4 g_wt1[K4N * HID];        // [40][128]
__device__ float4 g_wt2[K4N * OUTC];       // [40][64]

__device__ int4 g_cnt_row4[PADN/4];        // INVARIANT: zero at kernel_launch entry
__device__ int4 g_cnt_col4[PADN/4];        // (zero-init + cleanup at pipeline end)
__device__ int  g_cur_row[NN];
__device__ int  g_cur_col[NN];
__device__ int4 g_base_row4[PADN/4 + 1];
__device__ int4 g_base_col4[PADN/4 + 1];
__device__ int  g_csr_row_e[EE];   // edge ids sorted by row (agg gather)
__device__ int2 g_csr_col  [EE];   // {src, bits(dinv[src])} sorted by col

#define g_deg      ((float*)g_deg4)
#define g_cnt_row  ((int*)g_cnt_row4)
#define g_cnt_col  ((int*)g_cnt_col4)
#define g_base_row ((int*)g_base_row4)
#define g_base_col ((int*)g_base_col4)

// ---------------- f32x2 packed-FMA helpers (sm_103a FFMA2, PTX-only) --------
#define FMA_F32X2(d, a, b, c) \
    asm("fma.rn.f32x2 %0, %1, %2, %3;" : "=l"(d) : "l"(a), "l"(b), "l"(c))
#define BCAST_F32X2(d, f) \
    asm("mov.b64 %0, {%1, %1};" : "=l"(d) : "r"(__float_as_uint(f)))
#define UNPACK_F32X2(lo, hi, v) \
    asm("mov.b64 {%0, %1}, %2;" : "=r"(lo), "=r"(hi) : "l"(v))

__device__ __forceinline__ float f4c(const float4& v, int k) {
    return k == 0 ? v.x : (k == 1 ? v.y : (k == 2 ? v.z : v.w));
}

// ---------------- helpers ---------------------------------------------------
__device__ __forceinline__ long long getidx(const void* ei, long long pos, int is64) {
    if (is64) return ((const long long*)ei)[pos];
    return (long long)((const int*)ei)[pos];
}

// int64 vs int32 detection from the first 512 bytes: if data is int32, an
// 8-byte read packs two ids and is >= 2^32 unless the hi word is 0.
__device__ __forceinline__ int detect64(const void* ei) {
    const longlong4* p = (const longlong4*)ei;
    int ok = 1;
#pragma unroll
    for (int i = 0; i < 16; ++i) {
        longlong4 v = p[i];
        ok &= (v.x >= 0 && v.x < NN) & (v.y >= 0 && v.y < NN)
            & (v.z >= 0 && v.z < NN) & (v.w >= 0 && v.w < NN);
    }
    return ok;
}

// ---------------- 1: degree histograms (4 edges/thread) + weight repack ------
#define E4 (EE / 4)                          // 400000
#define EBLOCKS4 ((E4 + 255) / 256)          // 1563
#define WTTHREADS (K4N * HID + K4N * OUTC)   // 7680
#define WTBLOCKS ((WTTHREADS + 255) / 256)   // 30
__global__ __launch_bounds__(256) void hist_kernel(const void* __restrict__ ei,
                                                   const float* __restrict__ w1,
                                                   const float* __restrict__ w2) {
    if (blockIdx.x >= EBLOCKS4) {   // weight-repack tail blocks
        int tid = (blockIdx.x - EBLOCKS4) * 256 + threadIdx.x;
        if (tid < K4N * HID) {
            int k4 = tid >> 7, c = tid & 127;
            float4 v;
            v.x = w1[(4 * k4 + 0) * HID + c];
            v.y = w1[(4 * k4 + 1) * HID + c];
            v.z = w1[(4 * k4 + 2) * HID + c];
            v.w = w1[(4 * k4 + 3) * HID + c];
            g_wt1[k4 * HID + c] = v;
        }
        int t2 = tid - K4N * HID;
        if (t2 >= 0 && t2 < K4N * OUTC) {
            int k4 = t2 >> 6, c = t2 & 63;
            float4 v;
            v.x = w2[(4 * k4 + 0) * OUTC + c];
            v.y = w2[(4 * k4 + 1) * OUTC + c];
            v.z = w2[(4 * k4 + 2) * OUTC + c];
            v.w = w2[(4 * k4 + 3) * OUTC + c];
            g_wt2[k4 * OUTC + c] = v;
        }
        return;
    }
    __shared__ int s64;
    if (threadIdx.x == 0) s64 = detect64(ei);
    __syncthreads();
    const int t = blockIdx.x * 256 + threadIdx.x;
    if (t >= E4) return;
    if (s64) {
        const longlong4 r = ((const longlong4*)ei)[t];
        const longlong4 c = ((const longlong4*)ei)[E4 + t];
        atomicAdd(&g_cnt_row[(int)r.x], 1); atomicAdd(&g_cnt_row[(int)r.y], 1);
        atomicAdd(&g_cnt_row[(int)r.z], 1); atomicAdd(&g_cnt_row[(int)r.w], 1);
        atomicAdd(&g_cnt_col[(int)c.x], 1); atomicAdd(&g_cnt_col[(int)c.y], 1);
        atomicAdd(&g_cnt_col[(int)c.z], 1); atomicAdd(&g_cnt_col[(int)c.w], 1);
    } else {
        const int4 r = ((const int4*)ei)[t];
        const int4 c = ((const int4*)ei)[E4 + t];
        atomicAdd(&g_cnt_row[r.x], 1); atomicAdd(&g_cnt_row[r.y], 1);
        atomicAdd(&g_cnt_row[r.z], 1); atomicAdd(&g_cnt_row[r.w], 1);
        atomicAdd(&g_cnt_col[c.x], 1); atomicAdd(&g_cnt_col[c.y], 1);
        atomicAdd(&g_cnt_col[c.z], 1); atomicAdd(&g_cnt_col[c.w], 1);
    }
}

// ---------------- 2: exclusive scan + dinv (one block per array) ------------
__global__ __launch_bounds__(1024, 1) void scan_kernel() {
    const int4* c4 = (blockIdx.x == 0) ? g_cnt_row4 : g_cnt_col4;
    int4* b4       = (blockIdx.x == 0) ? g_base_row4 : g_base_col4;
    const int t = threadIdx.x;
    constexpr int PER4 = PADN / 4 / 1024;   // 25 int4 per thread

    int s = 0;
#pragma unroll
    for (int i = 0; i < PER4; ++i) {
        int4 q = c4[t * PER4 + i];
        s += q.x + q.y + q.z + q.w;
    }
    __shared__ int sm[1024];
    sm[t] = s;
    __syncthreads();
    for (int off = 1; off < 1024; off <<= 1) {
        int u = (t >= off) ? sm[t - off] : 0;
        __syncthreads();
        sm[t] += u;
        __syncthreads();
    }
    int run = sm[t] - s;   // exclusive prefix
#pragma unroll
    for (int i = 0; i < PER4; ++i) {
        int4 q = c4[t * PER4 + i];
        int4 b;
        b.x = run;
        b.y = b.x + q.x;
        b.z = b.y + q.y;
        b.w = b.z + q.z;
        run = b.w + q.w;
        b4[t * PER4 + i] = b;
    }
    if (blockIdx.x == 1) {   // dinv = rsqrt(in_degree + 1), fused
#pragma unroll
        for (int i = 0; i < PER4; ++i) {
            int4 q = c4[t * PER4 + i];
            float4 d;
            d.x = rsqrtf((float)(q.x + 1));
            d.y = rsqrtf((float)(q.y + 1));
            d.z = rsqrtf((float)(q.z + 1));
            d.w = rsqrtf((float)(q.w + 1));
            g_deg4[t * PER4 + i] = d;
        }
    }
}

// ---------------- 3: build both CSRs; col-CSR packs {src, dinv[src]} ---------
#define EBLOCKS ((EE + 255) / 256)   // 6250
__global__ __launch_bounds__(256) void reorder_kernel(const void* __restrict__ ei) {
    __shared__ int s64;
    if (threadIdx.x == 0) s64 = detect64(ei);
    __syncthreads();
    const int is64 = s64;
    long long e = (long long)blockIdx.x * blockDim.x + threadIdx.x;
    if (e >= EE) return;
    const int r = (int)getidx(ei, e, is64);
    const int c = (int)getidx(ei, EE + e, is64);
    int p = atomicAdd(&g_cur_row[r], 1);
    g_csr_row_e[g_base_row[r] + p] = (int)e;
    int q = atomicAdd(&g_cur_col[c], 1);
    g_csr_col[g_base_col[c] + q] = make_int2(r, __float_as_int(g_deg[r]));
}

// ---------------- 4 (PROFILED, control): agg[n] = sum edge_attr, row==n ------
#define WBLOCKS ((NN * 32 + 255) / 256)   // 12500
__global__ __launch_bounds__(256) void agg_gather_kernel(const float4* __restrict__ eattr) {
    const int warp = (blockIdx.x * blockDim.x + threadIdx.x) >> 5;
    if (warp >= NN) return;
    const int lane = threadIdx.x & 31;
    const int c = lane & 7;
    const int g = lane >> 3;
    const int beg = g_base_row[warp], end = g_base_row[warp + 1];
    float4 a0 = make_float4(0.f, 0.f, 0.f, 0.f);
    float4 a1 = make_float4(0.f, 0.f, 0.f, 0.f);
    int i = beg + g;
    for (; i + 12 < end; i += 16) {
        const int e0 = g_csr_row_e[i];
        const int e1 = g_csr_row_e[i + 4];
        const int e2 = g_csr_row_e[i + 8];
        const int e3 = g_csr_row_e[i + 12];
        const float4 v0 = eattr[(long long)e0 * 8 + c];
        const float4 v1 = eattr[(long long)e1 * 8 + c];
        const float4 v2 = eattr[(long long)e2 * 8 + c];
        const float4 v3 = eattr[(long long)e3 * 8 + c];
        a0.x += v0.x; a0.y += v0.y; a0.z += v0.z; a0.w += v0.w;
        a1.x += v1.x; a1.y += v1.y; a1.z += v1.z; a1.w += v1.w;
        a0.x += v2.x; a0.y += v2.y; a0.z += v2.z; a0.w += v2.w;
        a1.x += v3.x; a1.y += v3.y; a1.z += v3.z; a1.w += v3.w;
    }
    for (; i < end; i += 4) {
        const float4 v = eattr[(long long)g_csr_row_e[i] * 8 + c];
        a0.x += v.x; a0.y += v.y; a0.z += v.z; a0.w += v.w;
    }
    a0.x += a1.x; a0.y += a1.y; a0.z += a1.z; a0.w += a1.w;
#pragma unroll
    for (int off = 8; off <= 16; off <<= 1) {
        a0.x += __shfl_xor_sync(0xffffffffu, a0.x, off);
        a0.y += __shfl_xor_sync(0xffffffffu, a0.y, off);
        a0.z += __shfl_xor_sync(0xffffffffu, a0.z, off);
        a0.w += __shfl_xor_sync(0xffffffffu, a0.w, off);
    }
    if (lane < 8) g_agg[warp * 8 + c] = a0;
}

// ---------------- GEMM (f32x2): out[N,OC] = [A | agg] @ W --------------------
// 256 threads, 64-node tile. Input staged K-MAJOR in smem (LDS.128 broadcast).
// Weights in k4-major packed layout: warp weight reads fully coalesced.
template <int OC, int CA, bool RELU, bool SRC_OUT1>
__global__ __launch_bounds__(256) void gemm_kernel(const float* __restrict__ Aext) {
    constexpr int K = CA + FE;              // 160
    constexpr int K4 = K / 4;               // 40
    constexpr int CA4 = CA / 4;
    constexpr int TN = 64;
    constexpr int CPT = OC / 64;            // cols per thread: 2 or 1

    const float4* A4  = SRC_OUT1 ? (const float4*)g_out1 : (const float4*)Aext;
    const float4* WT4 = (OC == 128) ? g_wt1 : g_wt2;
    float*        Out = (OC == 128) ? (float*)g_h1 : (float*)g_h2;

    __shared__ float smk[K * TN];           // [k][n], 40960 B
    const int tid = threadIdx.x;
    const long long nb = (long long)blockIdx.x * TN;

    for (int idx = tid; idx < TN * CA4; idx += 256) {
        const int n = idx & 63, kk = idx >> 6;
        const long long node = nb + n;
        float4 v = make_float4(0.f, 0.f, 0.f, 0.f);
        if (node < NN) {
            v = A4[node * CA4 + kk];
            if (RELU) {
                v.x = fmaxf(v.x, 0.f); v.y = fmaxf(v.y, 0.f);
                v.z = fmaxf(v.z, 0.f); v.w = fmaxf(v.w, 0.f);
            }
        }
        smk[(4 * kk + 0) * TN + n] = v.x;
        smk[(4 * kk + 1) * TN + n] = v.y;
        smk[(4 * kk + 2) * TN + n] = v.z;
        smk[(4 * kk + 3) * TN + n] = v.w;
    }
    for (int idx = tid; idx < TN * 8; idx += 256) {
        const int n = idx & 63, kk = idx >> 6;
        const long long node = nb + n;
        float4 v = (node < NN) ? g_agg[node * 8 + kk]
                               : make_float4(0.f, 0.f, 0.f, 0.f);
        smk[(CA + 4 * kk + 0) * TN + n] = v.x;
        smk[(CA + 4 * kk + 1) * TN + n] = v.y;
        smk[(CA + 4 * kk + 2) * TN + n] = v.z;
        smk[(CA + 4 * kk + 3) * TN + n] = v.w;
    }
    __syncthreads();

    const int c0  = tid & 63;
    const int seg = tid >> 6;               // 4 segs x 16 nodes
    unsigned long long acc[CPT][8];
#pragma unroll
    for (int p = 0; p < CPT; ++p)
#pragma unroll
        for (int q = 0; q < 8; ++q) acc[p][q] = 0ull;

    const float* base = smk + seg * 16;
#pragma unroll 2
    for (int k4 = 0; k4 < K4; ++k4) {
        float4 wv[CPT];
#pragma unroll
        for (int p = 0; p < CPT; ++p) wv[p] = WT4[k4 * OC + c0 + 64 * p];
#pragma unroll
        for (int kk = 0; kk < 4; ++kk) {
            const longlong2* rk = (const longlong2*)(base + (4 * k4 + kk) * TN);
            const longlong2 q0 = rk[0];
            const longlong2 q1 = rk[1];
            const longlong2 q2 = rk[2];
            const longlong2 q3 = rk[3];
#pragma unroll
            for (int p = 0; p < CPT; ++p) {
                unsigned long long wp;
                BCAST_F32X2(wp, f4c(wv[p], kk));
                FMA_F32X2(acc[p][0], (unsigned long long)q0.x, wp, acc[p][0]);
                FMA_F32X2(acc[p][1], (unsigned long long)q0.y, wp, acc[p][1]);
                FMA_F32X2(acc[p][2], (unsigned long long)q1.x, wp, acc[p][2]);
                FMA_F32X2(acc[p][3], (unsigned long long)q1.y, wp, acc[p][3]);
                FMA_F32X2(acc[p][4], (unsigned long long)q2.x, wp, acc[p][4]);
                FMA_F32X2(acc[p][5], (unsigned long long)q2.y, wp, acc[p][5]);
                FMA_F32X2(acc[p][6], (unsigned long long)q3.x, wp, acc[p][6]);
                FMA_F32X2(acc[p][7], (unsigned long long)q3.y, wp, acc[p][7]);
            }
        }
    }

#pragma unroll
    for (int q = 0; q < 8; ++q) {
        const long long n0 = nb + seg * 16 + 2 * q;
#pragma unroll
        for (int p = 0; p < CPT; ++p) {
            unsigned int lo, hi;
            UNPACK_F32X2(lo, hi, acc[p][q]);
            if (n0 < NN)     Out[n0 * OC + c0 + 64 * p]       = __uint_as_float(lo);
            if (n0 + 1 < NN) Out[(n0 + 1) * OC + c0 + 64 * p] = __uint_as_float(hi);
        }
    }
}

// ---------------- layer gather, 128-dim: warp per node, MLP 4 ----------------
// out1[n] = b + dinv[n]*sum(dinv[s]*h1[s]) + dinv[n]^2*h1[n]
// col-CSR already carries {src, dinv[src]} -> one coalesced 8B load per slot.
__global__ __launch_bounds__(256) void gather128_kernel(const float* __restrict__ bias) {
    const float4* h = g_h1;
    float4* out = g_out1;
    const int n = (blockIdx.x * blockDim.x + threadIdx.x) >> 5;
    if (n >= NN) return;
    const int lane = threadIdx.x & 31;
    const int beg = g_base_col[n], end = g_base_col[n + 1];
    float4 acc0 = make_float4(0.f, 0.f, 0.f, 0.f);
    float4 acc1 = make_float4(0.f, 0.f, 0.f, 0.f);
    for (int i0 = beg; i0 < end; i0 += 32) {
        const int slot = i0 + lane;
        int s = 0; float w = 0.f;
        if (slot < end) {
            const int2 sw = g_csr_col[slot];
            s = sw.x; w = __int_as_float(sw.y);
        }
        const int m = min(32, end - i0);
        for (int j = 0; j < m; j += 4) {
            const int   s0 = __shfl_sync(0xffffffffu, s, j);
            const int   s1 = __shfl_sync(0xffffffffu, s, j + 1);
            const int   s2 = __shfl_sync(0xffffffffu, s, j + 2);
            const int   s3 = __shfl_sync(0xffffffffu, s, j + 3);
            const float w0 = __shfl_sync(0xffffffffu, w, j);
            const float w1 = __shfl_sync(0xffffffffu, w, j + 1);
            const float w2 = __shfl_sync(0xffffffffu, w, j + 2);
            const float w3 = __shfl_sync(0xffffffffu, w, j + 3);
            const float4 v0 = h[(long long)s0 * 32 + lane];
            const float4 v1 = h[(long long)s1 * 32 + lane];
            const float4 v2 = h[(long long)s2 * 32 + lane];
            const float4 v3 = h[(long long)s3 * 32 + lane];
            acc0.x = fmaf(w0, v0.x, acc0.x); acc0.y = fmaf(w0, v0.y, acc0.y);
            acc0.z = fmaf(w0, v0.z, acc0.z); acc0.w = fmaf(w0, v0.w, acc0.w);
            acc1.x = fmaf(w1, v1.x, acc1.x); acc1.y = fmaf(w1, v1.y, acc1.y);
            acc1.z = fmaf(w1, v1.z, acc1.z); acc1.w = fmaf(w1, v1.w, acc1.w);
            acc0.x = fmaf(w2, v2.x, acc0.x); acc0.y = fmaf(w2, v2.y, acc0.y);
            acc0.z = fmaf(w2, v2.z, acc0.z); acc0.w = fmaf(w2, v2.w, acc0.w);
            acc1.x = fmaf(w3, v3.x, acc1.x); acc1.y = fmaf(w3, v3.y, acc1.y);
            acc1.z = fmaf(w3, v3.z, acc1.z); acc1.w = fmaf(w3, v3.w, acc1.w);
        }
    }
    acc0.x += acc1.x; acc0.y += acc1.y; acc0.z += acc1.z; acc0.w += acc1.w;
    const float dn = g_deg[n];
    const float d2 = dn * dn;
    const float4 self = h[(long long)n * 32 + lane];
    const float4 bb = ((const float4*)bias)[lane];
    float4 o;
    o.x = bb.x + dn * acc0.x + d2 * self.x;
    o.y = bb.y + dn * acc0.y + d2 * self.y;
    o.z = bb.z + dn * acc0.z + d2 * self.z;
    o.w = bb.w + dn * acc0.w + d2 * self.w;
    out[(long long)n * 32 + lane] = o;
}

// ---------------- layer gather, 64-dim + cleanup tail blocks -----------------
__global__ __launch_bounds__(256) void gather64_kernel(const float* __restrict__ bias,
                                                       float4* __restrict__ out) {
    if (blockIdx.x >= WBLOCKS) {   // cleanup: restore zero-counter invariant
        int tid = (blockIdx.x - WBLOCKS) * 256 + threadIdx.x;
        if (tid < PADN / 4) {
            g_cnt_row4[tid] = make_int4(0, 0, 0, 0);
            g_cnt_col4[tid] = make_int4(0, 0, 0, 0);
        }
        if (tid < NN) { g_cur_row[tid] = 0; g_cur_col[tid] = 0; }
        return;
    }
    const float4* h = g_h2;
    const int n = (blockIdx.x * blockDim.x + threadIdx.x) >> 5;
    if (n >= NN) return;
    const int lane = threadIdx.x & 31;
    const int c = lane & 15;
    const int g = lane >> 4;
    const int beg = g_base_col[n], end = g_base_col[n + 1];
    float4 acc0 = make_float4(0.f, 0.f, 0.f, 0.f);
    float4 acc1 = make_float4(0.f, 0.f, 0.f, 0.f);
    for (int i0 = beg; i0 < end; i0 += 32) {
        const int slot = i0 + lane;
        int s = 0; float w = 0.f;
        if (slot < end) {
            const int2 sw = g_csr_col[slot];
            s = sw.x; w = __int_as_float(sw.y);
        }
        const int m = min(32, end - i0);
        for (int j = 0; j < m; j += 8) {
            const int   s0 = __shfl_sync(0xffffffffu, s, j + g);
            const int   s1 = __shfl_sync(0xffffffffu, s, j + 2 + g);
            const int   s2 = __shfl_sync(0xffffffffu, s, j + 4 + g);
            const int   s3 = __shfl_sync(0xffffffffu, s, j + 6 + g);
            const float w0 = __shfl_sync(0xffffffffu, w, j + g);
            const float w1 = __shfl_sync(0xffffffffu, w, j + 2 + g);
            const float w2 = __shfl_sync(0xffffffffu, w, j + 4 + g);
            const float w3 = __shfl_sync(0xffffffffu, w, j + 6 + g);
            const float4 v0 = h[(long long)s0 * 16 + c];
            const float4 v1 = h[(long long)s1 * 16 + c];
            const float4 v2 = h[(long long)s2 * 16 + c];
            const float4 v3 = h[(long long)s3 * 16 + c];
            acc0.x = fmaf(w0, v0.x, acc0.x); acc0.y = fmaf(w0, v0.y, acc0.y);
            acc0.z = fmaf(w0, v0.z, acc0.z); acc0.w = fmaf(w0, v0.w, acc0.w);
            acc1.x = fmaf(w1, v1.x, acc1.x); acc1.y = fmaf(w1, v1.y, acc1.y);
            acc1.z = fmaf(w1, v1.z, acc1.z); acc1.w = fmaf(w1, v1.w, acc1.w);
            acc0.x = fmaf(w2, v2.x, acc0.x); acc0.y = fmaf(w2, v2.y, acc0.y);
            acc0.z = fmaf(w2, v2.z, acc0.z); acc0.w = fmaf(w2, v2.w, acc0.w);
            acc1.x = fmaf(w3, v3.x, acc1.x); acc1.y = fmaf(w3, v3.y, acc1.y);
            acc1.z = fmaf(w3, v3.z, acc1.z); acc1.w = fmaf(w3, v3.w, acc1.w);
        }
    }
    acc0.x += acc1.x; acc0.y += acc1.y; acc0.z += acc1.z; acc0.w += acc1.w;
    acc0.x += __shfl_xor_sync(0xffffffffu, acc0.x, 16);
    acc0.y += __shfl_xor_sync(0xffffffffu, acc0.y, 16);
    acc0.z += __shfl_xor_sync(0xffffffffu, acc0.z, 16);
    acc0.w += __shfl_xor_sync(0xffffffffu, acc0.w, 16);
    if (lane < 16) {
        const float dn = g_deg[n];
        const float d2 = dn * dn;
        const float4 self = h[(long long)n * 16 + c];
        const float4 bb = ((const float4*)bias)[c];
        float4 o;
        o.x = bb.x + dn * acc0.x + d2 * self.x;
        o.y = bb.y + dn * acc0.y + d2 * self.y;
        o.z = bb.z + dn * acc0.z + d2 * self.z;
        o.w = bb.w + dn * acc0.w + d2 * self.w;
        out[(long long)n * 16 + c] = o;
    }
}

// ---------------- launch -----------------------------------------------------
extern "C" void kernel_launch(void* const* d_in, const int* in_sizes, int n_in,
                              void* d_out, int out_size) {
    const float*  x    = (const float*)d_in[0];
    const void*   ei   = d_in[1];
    const float4* eatt = (const float4*)d_in[2];
    const float*  w1   = (const float*)d_in[3];
    const float*  b1   = (const float*)d_in[4];
    const float*  w2   = (const float*)d_in[5];
    const float*  b2   = (const float*)d_in[6];
    float* out = (float*)d_out;

    constexpr int T = 256;
    const unsigned gblocks = (NN + 63) / 64;            // 1563
    const unsigned cleanb  = (NN + T - 1) / T;          // 391

    hist_kernel<<<EBLOCKS4 + WTBLOCKS, T>>>(ei, w1, w2);        // 1 (+wt repack)
    scan_kernel<<<2, 1024>>>();                                 // 2 (+dinv)
    reorder_kernel<<<EBLOCKS, T>>>(ei);                         // 3 (packs dinv)
    agg_gather_kernel<<<WBLOCKS, T>>>(eatt);                    // 4  <- PROFILED

    gemm_kernel<HID, FN, false, false><<<gblocks, T>>>(x);      // 5: x -> g_h1
    gather128_kernel<<<WBLOCKS, T>>>(b1);                       // 6: g_h1 -> g_out1
    gemm_kernel<OUTC, HID, true, true><<<gblocks, T>>>(x);      // 7: g_out1 -> g_h2
    gather64_kernel<<<WBLOCKS + cleanb, T>>>(b2, (float4*)out); // 8 (+cleanup)
}

// round 10
// speedup vs baseline: 30.4119x; 1.1413x over previous
#include <cuda_runtime.h>
#include <cuda_bf16.h>

#define NN 100000
#define EE 1600000
#define FN 128
#define FE 32
#define HID 128
#define OUTC 64
#define PADN 102400   // NN padded (25600 int4)
#define K4N 40        // 160/4 k4 groups
#define NB 296        // fused-prep grid: 2 blocks/SM, co-resident (grid barrier!)

// ---------------- scratch (device globals; zero-initialized) -----------------
// RULE (R5): these symbols are ONLY referenced from device code. Host-side
// references bind the ATS-visible host shadow object -> silent C2C traffic.
__device__ float4 g_agg [NN * (FE/4)];
__device__ float4 g_deg4[PADN/4];          // dinv
__device__ float4 g_h1  [NN * (HID/4)];    // h1' = dinv * (x|agg)@w1
__device__ float4 g_out1[NN * (HID/4)];    // layer-1 output (raw)
__device__ float4 g_h2  [NN * (OUTC/4)];   // h2' = dinv * (out1|agg)@w2
__device__ float4 g_wt1[K4N * HID];        // k4-major packed w1
__device__ float4 g_wt2[K4N * OUTC];       // k4-major packed w2

__device__ int4 g_cnt_row4[PADN/4];        // INVARIANT: zero at entry
__device__ int4 g_cnt_col4[PADN/4];
__device__ int  g_cur_row[NN];             // INVARIANT: zero at entry
__device__ int  g_cur_col[NN];
__device__ int4 g_base_row4[PADN/4 + 1];
__device__ int4 g_base_col4[PADN/4 + 1];
__device__ int  g_csr_row_e  [EE];         // edge ids sorted by row
__device__ int  g_csr_col_src[EE];         // src node ids sorted by col
__device__ int  g_bsum[256];               // chunk sums: [0..99] row, [128..227] col

__device__ unsigned g_bar_cnt;             // grid barrier (self-resetting)
__device__ volatile unsigned g_bar_gen;

#define g_deg      ((float*)g_deg4)
#define g_cnt_row  ((int*)g_cnt_row4)
#define g_cnt_col  ((int*)g_cnt_col4)
#define g_base_row ((int*)g_base_row4)
#define g_base_col ((int*)g_base_col4)

// ---------------- f32x2 helpers (sm_103a FFMA2, PTX-only) --------------------
#define FMA_F32X2(d, a, b, c) \
    asm("fma.rn.f32x2 %0, %1, %2, %3;" : "=l"(d) : "l"(a), "l"(b), "l"(c))
#define MUL_F32X2(d, a, b) \
    asm("mul.rn.f32x2 %0, %1, %2;" : "=l"(d) : "l"(a), "l"(b))
#define BCAST_F32X2(d, f) \
    asm("mov.b64 %0, {%1, %1};" : "=l"(d) : "r"(__float_as_uint(f)))
#define PACK_F32X2(d, lo, hi) \
    asm("mov.b64 %0, {%1, %2};" : "=l"(d) : "r"(__float_as_uint(lo)), "r"(__float_as_uint(hi)))
#define UNPACK_F32X2(lo, hi, v) \
    asm("mov.b64 {%0, %1}, %2;" : "=r"(lo), "=r"(hi) : "l"(v))

__device__ __forceinline__ float f4c(const float4& v, int k) {
    return k == 0 ? v.x : (k == 1 ? v.y : (k == 2 ? v.z : v.w));
}

// ---------------- helpers ----------------------------------------------------
__device__ __forceinline__ long long getidx(const void* ei, long long pos, int is64) {
    if (is64) return ((const long long*)ei)[pos];
    return (long long)((const int*)ei)[pos];
}

__device__ __forceinline__ int detect64(const void* ei) {
    const longlong4* p = (const longlong4*)ei;
    int ok = 1;
#pragma unroll
    for (int i = 0; i < 16; ++i) {
        longlong4 v = p[i];
        ok &= (v.x >= 0 && v.x < NN) & (v.y >= 0 && v.y < NN)
            & (v.z >= 0 && v.z < NN) & (v.w >= 0 && v.w < NN);
    }
    return ok;
}

// Grid-wide barrier. SAFE ONLY because the kernel is launched with NB = 2*148
// blocks and __launch_bounds__(256, 2) guarantees full co-residency.
__device__ __forceinline__ void grid_barrier() {
    __syncthreads();
    if (threadIdx.x == 0) {
        __threadfence();                        // release (also invalidates L1)
        const unsigned gen = g_bar_gen;
        if (atomicAdd(&g_bar_cnt, 1u) == (unsigned)NB - 1u) {
            g_bar_cnt = 0;
            __threadfence();
            g_bar_gen = gen + 1u;
        } else {
            while (g_bar_gen == gen) { }
        }
        __threadfence();                        // acquire-side L1 invalidate
    }
    __syncthreads();
}

// ---------------- 1: fused prep: hist+repack | scan+dinv | reorder -----------
#define E4 (EE / 4)                          // 400000
#define WT1N (K4N * HID)                     // 5120
#define WTTHREADS (WT1N + K4N * OUTC)        // 7680
__global__ __launch_bounds__(256, 2) void prep_kernel(const void* __restrict__ ei,
                                                      const float* __restrict__ w1,
                                                      const float* __restrict__ w2) {
    __shared__ int s64;
    __shared__ int wsum[8];
    if (threadIdx.x == 0) s64 = detect64(ei);
    __syncthreads();
    const int is64 = s64;
    const int gtid = blockIdx.x * 256 + threadIdx.x;
    constexpr int GSTRIDE = NB * 256;        // 75776

    // -- Phase A: weight repack (first 7680 threads) + degree histograms --
    if (gtid < WT1N) {
        int k4 = gtid >> 7, c = gtid & 127;
        float4 v;
        v.x = w1[(4 * k4 + 0) * HID + c];
        v.y = w1[(4 * k4 + 1) * HID + c];
        v.z = w1[(4 * k4 + 2) * HID + c];
        v.w = w1[(4 * k4 + 3) * HID + c];
        g_wt1[k4 * HID + c] = v;
    } else if (gtid < WTTHREADS) {
        int t2 = gtid - WT1N;
        int k4 = t2 >> 6, c = t2 & 63;
        float4 v;
        v.x = w2[(4 * k4 + 0) * OUTC + c];
        v.y = w2[(4 * k4 + 1) * OUTC + c];
        v.z = w2[(4 * k4 + 2) * OUTC + c];
        v.w = w2[(4 * k4 + 3) * OUTC + c];
        g_wt2[k4 * OUTC + c] = v;
    }
    for (int t = gtid; t < E4; t += GSTRIDE) {
        if (is64) {
            const longlong4 r = ((const longlong4*)ei)[t];
            const longlong4 c = ((const longlong4*)ei)[E4 + t];
            atomicAdd(&g_cnt_row[(int)r.x], 1); atomicAdd(&g_cnt_row[(int)r.y], 1);
            atomicAdd(&g_cnt_row[(int)r.z], 1); atomicAdd(&g_cnt_row[(int)r.w], 1);
            atomicAdd(&g_cnt_col[(int)c.x], 1); atomicAdd(&g_cnt_col[(int)c.y], 1);
            atomicAdd(&g_cnt_col[(int)c.z], 1); atomicAdd(&g_cnt_col[(int)c.w], 1);
        } else {
            const int4 r = ((const int4*)ei)[t];
            const int4 c = ((const int4*)ei)[E4 + t];
            atomicAdd(&g_cnt_row[r.x], 1); atomicAdd(&g_cnt_row[r.y], 1);
            atomicAdd(&g_cnt_row[r.z], 1); atomicAdd(&g_cnt_row[r.w], 1);
            atomicAdd(&g_cnt_col[c.x], 1); atomicAdd(&g_cnt_col[c.y], 1);
            atomicAdd(&g_cnt_col[c.z], 1); atomicAdd(&g_cnt_col[c.w], 1);
        }
    }
    grid_barrier();

    // -- Phase B1: 200 blocks scan 1024-int chunks (exclusive within chunk) --
    if (blockIdx.x < 200) {
        const int arr = blockIdx.x / 100;    // 0=row, 1=col
        const int chunk = blockIdx.x % 100;
        const int4* c4 = arr ? g_cnt_col4 : g_cnt_row4;
        int4* b4 = arr ? g_base_col4 : g_base_row4;
        const int idx = chunk * 256 + threadIdx.x;   // int4 index < 25600
        const int4 q = c4[idx];
        const int tsum = q.x + q.y + q.z + q.w;
        int inc = tsum;
        const int lane = threadIdx.x & 31, wd = threadIdx.x >> 5;
#pragma unroll
        for (int o = 1; o < 32; o <<= 1) {
            int u = __shfl_up_sync(0xffffffffu, inc, o);
            if (lane >= o) inc += u;
        }
        if (lane == 31) wsum[wd] = inc;
        __syncthreads();
        if (threadIdx.x == 0) {
            int r = 0;
#pragma unroll
            for (int i = 0; i < 8; ++i) { int v = wsum[i]; wsum[i] = r; r += v; }
            g_bsum[arr * 128 + chunk] = r;   // chunk total
        }
        __syncthreads();
        const int exc = wsum[wd] + inc - tsum;
        int4 b;
        b.x = exc; b.y = b.x + q.x; b.z = b.y + q.y; b.w = b.z + q.z;
        b4[idx] = b;
        if (arr == 1) {                      // dinv = rsqrt(in_deg + 1)
            float4 d;
            d.x = rsqrtf((float)(q.x + 1));
            d.y = rsqrtf((float)(q.y + 1));
            d.z = rsqrtf((float)(q.z + 1));
            d.w = rsqrtf((float)(q.w + 1));
            g_deg4[idx] = d;
        }
    }
    grid_barrier();

    // -- Phase B2: block 0 scans the 2x100 chunk totals --
    if (blockIdx.x == 0 && threadIdx.x < 2) {
        const int arr = threadIdx.x;
        int r = 0;
        for (int i = 0; i < 100; ++i) {
            int v = __ldcg(&g_bsum[arr * 128 + i]);
            g_bsum[arr * 128 + i] = r;
            r += v;
        }
    }
    grid_barrier();

    // -- Phase B3: add chunk offsets --
    if (blockIdx.x < 200) {
        const int arr = blockIdx.x / 100;
        const int chunk = blockIdx.x % 100;
        int4* b4 = arr ? g_base_col4 : g_base_row4;
        const int idx = chunk * 256 + threadIdx.x;
        const int off = __ldcg(&g_bsum[arr * 128 + chunk]);
        int4 b = b4[idx];
        b.x += off; b.y += off; b.z += off; b.w += off;
        b4[idx] = b;
    }
    grid_barrier();

    // -- Phase C: build both CSRs; restore cnt-zero invariant --
    for (long long e = gtid; e < EE; e += GSTRIDE) {
        const int r = (int)getidx(ei, e, is64);
        const int c = (int)getidx(ei, EE + e, is64);
        int p = atomicAdd(&g_cur_row[r], 1);
        g_csr_row_e[g_base_row[r] + p] = (int)e;
        int q = atomicAdd(&g_cur_col[c], 1);
        g_csr_col_src[g_base_col[c] + q] = r;
    }
    for (int t = gtid; t < PADN / 4; t += GSTRIDE) {
        g_cnt_row4[t] = make_int4(0, 0, 0, 0);
        g_cnt_col4[t] = make_int4(0, 0, 0, 0);
    }
}

// ---------------- 2: agg[n] = sum edge_attr over row==n ----------------------
#define WBLOCKS ((NN * 32 + 255) / 256)   // 12500
__global__ __launch_bounds__(256) void agg_gather_kernel(const float4* __restrict__ eattr) {
    const int warp = (blockIdx.x * blockDim.x + threadIdx.x) >> 5;
    if (warp >= NN) return;
    const int lane = threadIdx.x & 31;
    const int c = lane & 7;
    const int g = lane >> 3;
    const int beg = g_base_row[warp], end = g_base_row[warp + 1];
    float4 a0 = make_float4(0.f, 0.f, 0.f, 0.f);
    float4 a1 = make_float4(0.f, 0.f, 0.f, 0.f);
    int i = beg + g;
    for (; i + 12 < end; i += 16) {
        const int e0 = g_csr_row_e[i];
        const int e1 = g_csr_row_e[i + 4];
        const int e2 = g_csr_row_e[i + 8];
        const int e3 = g_csr_row_e[i + 12];
        const float4 v0 = eattr[(long long)e0 * 8 + c];
        const float4 v1 = eattr[(long long)e1 * 8 + c];
        const float4 v2 = eattr[(long long)e2 * 8 + c];
        const float4 v3 = eattr[(long long)e3 * 8 + c];
        a0.x += v0.x; a0.y += v0.y; a0.z += v0.z; a0.w += v0.w;
        a1.x += v1.x; a1.y += v1.y; a1.z += v1.z; a1.w += v1.w;
        a0.x += v2.x; a0.y += v2.y; a0.z += v2.z; a0.w += v2.w;
        a1.x += v3.x; a1.y += v3.y; a1.z += v3.z; a1.w += v3.w;
    }
    for (; i < end; i += 4) {
        const float4 v = eattr[(long long)g_csr_row_e[i] * 8 + c];
        a0.x += v.x; a0.y += v.y; a0.z += v.z; a0.w += v.w;
    }
    a0.x += a1.x; a0.y += a1.y; a0.z += a1.z; a0.w += a1.w;
#pragma unroll
    for (int off = 8; off <= 16; off <<= 1) {
        a0.x += __shfl_xor_sync(0xffffffffu, a0.x, off);
        a0.y += __shfl_xor_sync(0xffffffffu, a0.y, off);
        a0.z += __shfl_xor_sync(0xffffffffu, a0.z, off);
        a0.w += __shfl_xor_sync(0xffffffffu, a0.w, off);
    }
    if (lane < 8) g_agg[warp * 8 + c] = a0;
}

// ---------------- GEMM (f32x2): out[N,OC] = dinv * ([A|agg] @ W) -------------
// 256 threads, 64-node tile. Input staged K-MAJOR in smem; weights k4-major
// coalesced; epilogue scales each output row by dinv (prescaled-h trick).
template <int OC, int CA, bool RELU, bool SRC_OUT1>
__global__ __launch_bounds__(256) void gemm_kernel(const float* __restrict__ Aext) {
    constexpr int K = CA + FE;              // 160
    constexpr int K4 = K / 4;               // 40
    constexpr int CA4 = CA / 4;
    constexpr int TN = 64;
    constexpr int CPT = OC / 64;

    const float4* A4  = SRC_OUT1 ? (const float4*)g_out1 : (const float4*)Aext;
    const float4* WT4 = (OC == 128) ? g_wt1 : g_wt2;
    float*        Out = (OC == 128) ? (float*)g_h1 : (float*)g_h2;

    __shared__ float smk[K * TN];           // 40960 B
    __shared__ float sdeg[TN];
    const int tid = threadIdx.x;
    const long long nb = (long long)blockIdx.x * TN;

    if (tid < TN) {
        const long long node = nb + tid;
        sdeg[tid] = (node < NN) ? g_deg[node] : 0.f;
    }
    for (int idx = tid; idx < TN * CA4; idx += 256) {
        const int n = idx & 63, kk = idx >> 6;
        const long long node = nb + n;
        float4 v = make_float4(0.f, 0.f, 0.f, 0.f);
        if (node < NN) {
            v = A4[node * CA4 + kk];
            if (RELU) {
                v.x = fmaxf(v.x, 0.f); v.y = fmaxf(v.y, 0.f);
                v.z = fmaxf(v.z, 0.f); v.w = fmaxf(v.w, 0.f);
            }
        }
        smk[(4 * kk + 0) * TN + n] = v.x;
        smk[(4 * kk + 1) * TN + n] = v.y;
        smk[(4 * kk + 2) * TN + n] = v.z;
        smk[(4 * kk + 3) * TN + n] = v.w;
    }
    for (int idx = tid; idx < TN * 8; idx += 256) {
        const int n = idx & 63, kk = idx >> 6;
        const long long node = nb + n;
        float4 v = (node < NN) ? g_agg[node * 8 + kk]
                               : make_float4(0.f, 0.f, 0.f, 0.f);
        smk[(CA + 4 * kk + 0) * TN + n] = v.x;
        smk[(CA + 4 * kk + 1) * TN + n] = v.y;
        smk[(CA + 4 * kk + 2) * TN + n] = v.z;
        smk[(CA + 4 * kk + 3) * TN + n] = v.w;
    }
    __syncthreads();

    const int c0  = tid & 63;
    const int seg = tid >> 6;
    unsigned long long acc[CPT][8];
#pragma unroll
    for (int p = 0; p < CPT; ++p)
#pragma unroll
        for (int q = 0; q < 8; ++q) acc[p][q] = 0ull;

    const float* base = smk + seg * 16;
#pragma unroll 2
    for (int k4 = 0; k4 < K4; ++k4) {
        float4 wv[CPT];
#pragma unroll
        for (int p = 0; p < CPT; ++p) wv[p] = WT4[k4 * OC + c0 + 64 * p];
#pragma unroll
        for (int kk = 0; kk < 4; ++kk) {
            const longlong2* rk = (const longlong2*)(base + (4 * k4 + kk) * TN);
            const longlong2 q0 = rk[0];
            const longlong2 q1 = rk[1];
            const longlong2 q2 = rk[2];
            const longlong2 q3 = rk[3];
#pragma unroll
            for (int p = 0; p < CPT; ++p) {
                unsigned long long wp;
                BCAST_F32X2(wp, f4c(wv[p], kk));
                FMA_F32X2(acc[p][0], (unsigned long long)q0.x, wp, acc[p][0]);
                FMA_F32X2(acc[p][1], (unsigned long long)q0.y, wp, acc[p][1]);
                FMA_F32X2(acc[p][2], (unsigned long long)q1.x, wp, acc[p][2]);
                FMA_F32X2(acc[p][3], (unsigned long long)q1.y, wp, acc[p][3]);
                FMA_F32X2(acc[p][4], (unsigned long long)q2.x, wp, acc[p][4]);
                FMA_F32X2(acc[p][5], (unsigned long long)q2.y, wp, acc[p][5]);
                FMA_F32X2(acc[p][6], (unsigned long long)q3.x, wp, acc[p][6]);
                FMA_F32X2(acc[p][7], (unsigned long long)q3.y, wp, acc[p][7]);
            }
        }
    }

#pragma unroll
    for (int q = 0; q < 8; ++q) {
        const long long n0 = nb + seg * 16 + 2 * q;
        unsigned long long dd;
        PACK_F32X2(dd, sdeg[seg * 16 + 2 * q], sdeg[seg * 16 + 2 * q + 1]);
#pragma unroll
        for (int p = 0; p < CPT; ++p) {
            unsigned long long sc;
            MUL_F32X2(sc, acc[p][q], dd);
            unsigned int lo, hi;
            UNPACK_F32X2(lo, hi, sc);
            if (n0 < NN)     Out[n0 * OC + c0 + 64 * p]       = __uint_as_float(lo);
            if (n0 + 1 < NN) Out[(n0 + 1) * OC + c0 + 64 * p] = __uint_as_float(hi);
        }
    }
}

// ---------------- 4 (PROFILED): gather 128-dim, pure unweighted row sum ------
// out1[n] = b1 + dinv[n] * (h1'[n] + sum_{s in col-CSR[n]} h1'[s])
__global__ __launch_bounds__(256) void gather128_kernel(const float* __restrict__ bias) {
    const float4* h = g_h1;
    float4* out = g_out1;
    const int n = (blockIdx.x * blockDim.x + threadIdx.x) >> 5;
    if (n >= NN) return;
    const int lane = threadIdx.x & 31;
    const int beg = g_base_col[n], end = g_base_col[n + 1];
    float4 acc0 = make_float4(0.f, 0.f, 0.f, 0.f);
    float4 acc1 = make_float4(0.f, 0.f, 0.f, 0.f);
    for (int i0 = beg; i0 < end; i0 += 32) {
        const int slot = i0 + lane;
        const int s = (slot < end) ? g_csr_col_src[slot] : 0;
        const int m = min(32, end - i0);
        int j = 0;
        for (; j + 4 <= m; j += 4) {
            const int s0 = __shfl_sync(0xffffffffu, s, j);
            const int s1 = __shfl_sync(0xffffffffu, s, j + 1);
            const int s2 = __shfl_sync(0xffffffffu, s, j + 2);
            const int s3 = __shfl_sync(0xffffffffu, s, j + 3);
            const float4 v0 = h[(long long)s0 * 32 + lane];
            const float4 v1 = h[(long long)s1 * 32 + lane];
            const float4 v2 = h[(long long)s2 * 32 + lane];
            const float4 v3 = h[(long long)s3 * 32 + lane];
            acc0.x += v0.x; acc0.y += v0.y; acc0.z += v0.z; acc0.w += v0.w;
            acc1.x += v1.x; acc1.y += v1.y; acc1.z += v1.z; acc1.w += v1.w;
            acc0.x += v2.x; acc0.y += v2.y; acc0.z += v2.z; acc0.w += v2.w;
            acc1.x += v3.x; acc1.y += v3.y; acc1.z += v3.z; acc1.w += v3.w;
        }
        for (; j < m; ++j) {                 // remainder (<= 3 edges, uniform j)
            const int s0 = __shfl_sync(0xffffffffu, s, j);
            const float4 v = h[(long long)s0 * 32 + lane];
            acc0.x += v.x; acc0.y += v.y; acc0.z += v.z; acc0.w += v.w;
        }
    }
    acc0.x += acc1.x; acc0.y += acc1.y; acc0.z += acc1.z; acc0.w += acc1.w;
    const float dn = g_deg[n];
    const float4 self = h[(long long)n * 32 + lane];
    const float4 bb = ((const float4*)bias)[lane];
    float4 o;
    o.x = bb.x + dn * (acc0.x + self.x);
    o.y = bb.y + dn * (acc0.y + self.y);
    o.z = bb.z + dn * (acc0.z + self.z);
    o.w = bb.w + dn * (acc0.w + self.w);
    out[(long long)n * 32 + lane] = o;
}

// ---------------- 6: gather 64-dim (+ cursor cleanup tail) -------------------
__global__ __launch_bounds__(256) void gather64_kernel(const float* __restrict__ bias,
                                                       float4* __restrict__ out) {
    if (blockIdx.x >= WBLOCKS) {   // restore cur-zero invariant
        int tid = (blockIdx.x - WBLOCKS) * 256 + threadIdx.x;
        if (tid < NN) { g_cur_row[tid] = 0; g_cur_col[tid] = 0; }
        return;
    }
    const float4* h = g_h2;
    const int n = (blockIdx.x * blockDim.x + threadIdx.x) >> 5;
    if (n >= NN) return;
    const int lane = threadIdx.x & 31;
    const int c = lane & 15;
    const int g = lane >> 4;
    const int beg = g_base_col[n], end = g_base_col[n + 1];
    float4 acc0 = make_float4(0.f, 0.f, 0.f, 0.f);
    float4 acc1 = make_float4(0.f, 0.f, 0.f, 0.f);
    for (int i0 = beg; i0 < end; i0 += 32) {
        const int slot = i0 + lane;
        const int s = (slot < end) ? g_csr_col_src[slot] : 0;
        const int m = min(32, end - i0);
        int j = 0;
        for (; j + 8 <= m; j += 8) {
            const int s0 = __shfl_sync(0xffffffffu, s, j + g);
            const int s1 = __shfl_sync(0xffffffffu, s, j + 2 + g);
            const int s2 = __shfl_sync(0xffffffffu, s, j + 4 + g);
            const int s3 = __shfl_sync(0xffffffffu, s, j + 6 + g);
            const float4 v0 = h[(long long)s0 * 16 + c];
            const float4 v1 = h[(long long)s1 * 16 + c];
            const float4 v2 = h[(long long)s2 * 16 + c];
            const float4 v3 = h[(long long)s3 * 16 + c];
            acc0.x += v0.x; acc0.y += v0.y; acc0.z += v0.z; acc0.w += v0.w;
            acc1.x += v1.x; acc1.y += v1.y; acc1.z += v1.z; acc1.w += v1.w;
            acc0.x += v2.x; acc0.y += v2.y; acc0.z += v2.z; acc0.w += v2.w;
            acc1.x += v3.x; acc1.y += v3.y; acc1.z += v3.z; acc1.w += v3.w;
        }
        for (; j < m; j += 2) {              // remainder, half-warp pairs
            const int idx = j + g;
            const int idxc = min(idx, m - 1);
            const int s0 = __shfl_sync(0xffffffffu, s, idxc);
            const float4 v = h[(long long)s0 * 16 + c];
            if (idx < m) {
                acc0.x += v.x; acc0.y += v.y; acc0.z += v.z; acc0.w += v.w;
            }
        }
    }
    acc0.x += acc1.x; acc0.y += acc1.y; acc0.z += acc1.z; acc0.w += acc1.w;
    acc0.x += __shfl_xor_sync(0xffffffffu, acc0.x, 16);
    acc0.y += __shfl_xor_sync(0xffffffffu, acc0.y, 16);
    acc0.z += __shfl_xor_sync(0xffffffffu, acc0.z, 16);
    acc0.w += __shfl_xor_sync(0xffffffffu, acc0.w, 16);
    if (lane < 16) {
        const float dn = g_deg[n];
        const float4 self = h[(long long)n * 16 + c];
        const float4 bb = ((const float4*)bias)[c];
        float4 o;
        o.x = bb.x + dn * (acc0.x + self.x);
        o.y = bb.y + dn * (acc0.y + self.y);
        o.z = bb.z + dn * (acc0.z + self.z);
        o.w = bb.w + dn * (acc0.w + self.w);
        out[(long long)n * 16 + c] = o;
    }
}

// ---------------- launch -----------------------------------------------------
extern "C" void kernel_launch(void* const* d_in, const int* in_sizes, int n_in,
                              void* d_out, int out_size) {
    const float*  x    = (const float*)d_in[0];
    const void*   ei   = d_in[1];
    const float4* eatt = (const float4*)d_in[2];
    const float*  w1   = (const float*)d_in[3];
    const float*  b1   = (const float*)d_in[4];
    const float*  w2   = (const float*)d_in[5];
    const float*  b2   = (const float*)d_in[6];
    float* out = (float*)d_out;

    constexpr int T = 256;
    const unsigned gblocks = (NN + 63) / 64;            // 1563
    const unsigned cleanb  = (NN + T - 1) / T;          // 391

    prep_kernel<<<NB, T>>>(ei, w1, w2);                         // 1: full CSR prep
    agg_gather_kernel<<<WBLOCKS, T>>>(eatt);                    // 2
    gemm_kernel<HID, FN, false, false><<<gblocks, T>>>(x);      // 3: x -> h1'
    gather128_kernel<<<WBLOCKS, T>>>(b1);                       // 4  <- PROFILED
    gemm_kernel<OUTC, HID, true, true><<<gblocks, T>>>(x);      // 5: out1 -> h2'
    gather64_kernel<<<WBLOCKS + cleanb, T>>>(b2, (float4*)out); // 6 (+cur cleanup)
}

// round 11
// speedup vs baseline: 32.0850x; 1.0550x over previous
#include <cuda_runtime.h>
#include <cuda_fp16.h>

#define NN 100000
#define EE 1600000
#define FN 128
#define FE 32
#define HID 128
#define OUTC 64
#define PADN 102400   // NN padded (25600 int4)
#define K4N 40        // 160/4 k4 groups
#define NB 296        // fused-prep grid: 2 blocks/SM, co-resident (grid barrier!)

// ---------------- scratch (device globals; zero-initialized) -----------------
// RULE (R5): these symbols are ONLY referenced from device code. Host-side
// references bind the ATS-visible host shadow object -> silent C2C traffic.
__device__ float4 g_agg [NN * (FE/4)];
__device__ float4 g_deg4[PADN/4];          // dinv
__device__ __half g_h1h [NN * HID];        // h1' = dinv*(x|agg)@w1, fp16 messages
__device__ float4 g_out1[NN * (HID/4)];    // layer-1 output (fp32)
__device__ __half g_h2h [NN * OUTC];       // h2' = dinv*(out1|agg)@w2, fp16
__device__ float4 g_wt1[K4N * HID];        // k4-major packed w1
__device__ float4 g_wt2[K4N * OUTC];       // k4-major packed w2

__device__ int4 g_cnt_row4[PADN/4];        // INVARIANT: zero at entry
__device__ int4 g_cnt_col4[PADN/4];
__device__ int  g_cur_row[NN];             // INVARIANT: zero at entry
__device__ int  g_cur_col[NN];
__device__ int4 g_base_row4[PADN/4 + 1];
__device__ int4 g_base_col4[PADN/4 + 1];
__device__ int  g_csr_row_e  [EE];         // edge ids sorted by row
__device__ int  g_csr_col_src[EE];         // src node ids sorted by col
__device__ int  g_bsum[256];               // chunk sums: [0..99] row, [128..227] col

__device__ unsigned g_bar_cnt;             // grid barrier (self-resetting)
__device__ volatile unsigned g_bar_gen;

#define g_deg      ((float*)g_deg4)
#define g_cnt_row  ((int*)g_cnt_row4)
#define g_cnt_col  ((int*)g_cnt_col4)
#define g_base_row ((int*)g_base_row4)
#define g_base_col ((int*)g_base_col4)

// ---------------- f32x2 helpers (sm_103a FFMA2, PTX-only) --------------------
#define FMA_F32X2(d, a, b, c) \
    asm("fma.rn.f32x2 %0, %1, %2, %3;" : "=l"(d) : "l"(a), "l"(b), "l"(c))
#define MUL_F32X2(d, a, b) \
    asm("mul.rn.f32x2 %0, %1, %2;" : "=l"(d) : "l"(a), "l"(b))
#define BCAST_F32X2(d, f) \
    asm("mov.b64 %0, {%1, %1};" : "=l"(d) : "r"(__float_as_uint(f)))
#define PACK_F32X2(d, lo, hi) \
    asm("mov.b64 %0, {%1, %2};" : "=l"(d) : "r"(__float_as_uint(lo)), "r"(__float_as_uint(hi)))
#define UNPACK_F32X2(lo, hi, v) \
    asm("mov.b64 {%0, %1}, %2;" : "=r"(lo), "=r"(hi) : "l"(v))

__device__ __forceinline__ float f4c(const float4& v, int k) {
    return k == 0 ? v.x : (k == 1 ? v.y : (k == 2 ? v.z : v.w));
}

// accumulate 4 fp16 values (packed in uint2) into a float4
__device__ __forceinline__ void acc_h4(float4& a, uint2 u) {
    const float2 f0 = __half22float2(*reinterpret_cast<__half2*>(&u.x));
    const float2 f1 = __half22float2(*reinterpret_cast<__half2*>(&u.y));
    a.x += f0.x; a.y += f0.y; a.z += f1.x; a.w += f1.y;
}

// ---------------- helpers ----------------------------------------------------
__device__ __forceinline__ long long getidx(const void* ei, long long pos, int is64) {
    if (is64) return ((const long long*)ei)[pos];
    return (long long)((const int*)ei)[pos];
}

__device__ __forceinline__ int detect64(const void* ei) {
    const longlong4* p = (const longlong4*)ei;
    int ok = 1;
#pragma unroll
    for (int i = 0; i < 16; ++i) {
        longlong4 v = p[i];
        ok &= (v.x >= 0 && v.x < NN) & (v.y >= 0 && v.y < NN)
            & (v.z >= 0 && v.z < NN) & (v.w >= 0 && v.w < NN);
    }
    return ok;
}

// Grid-wide barrier. SAFE ONLY because the kernel launches NB = 2*148 blocks
// with __launch_bounds__(256, 2) guaranteeing full co-residency.
__device__ __forceinline__ void grid_barrier() {
    __syncthreads();
    if (threadIdx.x == 0) {
        __threadfence();
        const unsigned gen = g_bar_gen;
        if (atomicAdd(&g_bar_cnt, 1u) == (unsigned)NB - 1u) {
            g_bar_cnt = 0;
            __threadfence();
            g_bar_gen = gen + 1u;
        } else {
            while (g_bar_gen == gen) { }
        }
        __threadfence();
    }
    __syncthreads();
}

// ---------------- 1: fused prep: hist+repack | scan+dinv | reorder -----------
#define E4 (EE / 4)                          // 400000
#define WT1N (K4N * HID)                     // 5120
#define WTTHREADS (WT1N + K4N * OUTC)        // 7680
__global__ __launch_bounds__(256, 2) void prep_kernel(const void* __restrict__ ei,
                                                      const float* __restrict__ w1,
                                                      const float* __restrict__ w2) {
    __shared__ int s64;
    __shared__ int wsum[8];
    if (threadIdx.x == 0) s64 = detect64(ei);
    __syncthreads();
    const int is64 = s64;
    const int gtid = blockIdx.x * 256 + threadIdx.x;
    constexpr int GSTRIDE = NB * 256;        // 75776

    // -- Phase A: weight repack + degree histograms --
    if (gtid < WT1N) {
        int k4 = gtid >> 7, c = gtid & 127;
        float4 v;
        v.x = w1[(4 * k4 + 0) * HID + c];
        v.y = w1[(4 * k4 + 1) * HID + c];
        v.z = w1[(4 * k4 + 2) * HID + c];
        v.w = w1[(4 * k4 + 3) * HID + c];
        g_wt1[k4 * HID + c] = v;
    } else if (gtid < WTTHREADS) {
        int t2 = gtid - WT1N;
        int k4 = t2 >> 6, c = t2 & 63;
        float4 v;
        v.x = w2[(4 * k4 + 0) * OUTC + c];
        v.y = w2[(4 * k4 + 1) * OUTC + c];
        v.z = w2[(4 * k4 + 2) * OUTC + c];
        v.w = w2[(4 * k4 + 3) * OUTC + c];
        g_wt2[k4 * OUTC + c] = v;
    }
    for (int t = gtid; t < E4; t += GSTRIDE) {
        if (is64) {
            const longlong4 r = ((const longlong4*)ei)[t];
            const longlong4 c = ((const longlong4*)ei)[E4 + t];
            atomicAdd(&g_cnt_row[(int)r.x], 1); atomicAdd(&g_cnt_row[(int)r.y], 1);
            atomicAdd(&g_cnt_row[(int)r.z], 1); atomicAdd(&g_cnt_row[(int)r.w], 1);
            atomicAdd(&g_cnt_col[(int)c.x], 1); atomicAdd(&g_cnt_col[(int)c.y], 1);
            atomicAdd(&g_cnt_col[(int)c.z], 1); atomicAdd(&g_cnt_col[(int)c.w], 1);
        } else {
            const int4 r = ((const int4*)ei)[t];
            const int4 c = ((const int4*)ei)[E4 + t];
            atomicAdd(&g_cnt_row[r.x], 1); atomicAdd(&g_cnt_row[r.y], 1);
            atomicAdd(&g_cnt_row[r.z], 1); atomicAdd(&g_cnt_row[r.w], 1);
            atomicAdd(&g_cnt_col[c.x], 1); atomicAdd(&g_cnt_col[c.y], 1);
            atomicAdd(&g_cnt_col[c.z], 1); atomicAdd(&g_cnt_col[c.w], 1);
        }
    }
    grid_barrier();

    // -- Phase B1: 200 blocks scan 1024-int chunks --
    if (blockIdx.x < 200) {
        const int arr = blockIdx.x / 100;    // 0=row, 1=col
        const int chunk = blockIdx.x % 100;
        const int4* c4 = arr ? g_cnt_col4 : g_cnt_row4;
        int4* b4 = arr ? g_base_col4 : g_base_row4;
        const int idx = chunk * 256 + threadIdx.x;
        const int4 q = c4[idx];
        const int tsum = q.x + q.y + q.z + q.w;
        int inc = tsum;
        const int lane = threadIdx.x & 31, wd = threadIdx.x >> 5;
#pragma unroll
        for (int o = 1; o < 32; o <<= 1) {
            int u = __shfl_up_sync(0xffffffffu, inc, o);
            if (lane >= o) inc += u;
        }
        if (lane == 31) wsum[wd] = inc;
        __syncthreads();
        if (threadIdx.x == 0) {
            int r = 0;
#pragma unroll
            for (int i = 0; i < 8; ++i) { int v = wsum[i]; wsum[i] = r; r += v; }
            g_bsum[arr * 128 + chunk] = r;
        }
        __syncthreads();
        const int exc = wsum[wd] + inc - tsum;
        int4 b;
        b.x = exc; b.y = b.x + q.x; b.z = b.y + q.y; b.w = b.z + q.z;
        b4[idx] = b;
        if (arr == 1) {
            float4 d;
            d.x = rsqrtf((float)(q.x + 1));
            d.y = rsqrtf((float)(q.y + 1));
            d.z = rsqrtf((float)(q.z + 1));
            d.w = rsqrtf((float)(q.w + 1));
            g_deg4[idx] = d;
        }
    }
    grid_barrier();

    // -- Phase B2: block 0 scans chunk totals --
    if (blockIdx.x == 0 && threadIdx.x < 2) {
        const int arr = threadIdx.x;
        int r = 0;
        for (int i = 0; i < 100; ++i) {
            int v = __ldcg(&g_bsum[arr * 128 + i]);
            g_bsum[arr * 128 + i] = r;
            r += v;
        }
    }
    grid_barrier();

    // -- Phase B3: add chunk offsets --
    if (blockIdx.x < 200) {
        const int arr = blockIdx.x / 100;
        const int chunk = blockIdx.x % 100;
        int4* b4 = arr ? g_base_col4 : g_base_row4;
        const int idx = chunk * 256 + threadIdx.x;
        const int off = __ldcg(&g_bsum[arr * 128 + chunk]);
        int4 b = b4[idx];
        b.x += off; b.y += off; b.z += off; b.w += off;
        b4[idx] = b;
    }
    grid_barrier();

    // -- Phase C: build both CSRs; restore cnt-zero invariant --
    for (long long e = gtid; e < EE; e += GSTRIDE) {
        const int r = (int)getidx(ei, e, is64);
        const int c = (int)getidx(ei, EE + e, is64);
        int p = atomicAdd(&g_cur_row[r], 1);
        g_csr_row_e[g_base_row[r] + p] = (int)e;
        int q = atomicAdd(&g_cur_col[c], 1);
        g_csr_col_src[g_base_col[c] + q] = r;
    }
    for (int t = gtid; t < PADN / 4; t += GSTRIDE) {
        g_cnt_row4[t] = make_int4(0, 0, 0, 0);
        g_cnt_col4[t] = make_int4(0, 0, 0, 0);
    }
}

// ---------------- 2: agg[n] = sum edge_attr over row==n ----------------------
#define WBLOCKS ((NN * 32 + 255) / 256)   // 12500
__global__ __launch_bounds__(256) void agg_gather_kernel(const float4* __restrict__ eattr) {
    const int warp = (blockIdx.x * blockDim.x + threadIdx.x) >> 5;
    if (warp >= NN) return;
    const int lane = threadIdx.x & 31;
    const int c = lane & 7;
    const int g = lane >> 3;
    const int beg = g_base_row[warp], end = g_base_row[warp + 1];
    float4 a0 = make_float4(0.f, 0.f, 0.f, 0.f);
    float4 a1 = make_float4(0.f, 0.f, 0.f, 0.f);
    int i = beg + g;
    for (; i + 12 < end; i += 16) {
        const int e0 = g_csr_row_e[i];
        const int e1 = g_csr_row_e[i + 4];
        const int e2 = g_csr_row_e[i + 8];
        const int e3 = g_csr_row_e[i + 12];
        const float4 v0 = eattr[(long long)e0 * 8 + c];
        const float4 v1 = eattr[(long long)e1 * 8 + c];
        const float4 v2 = eattr[(long long)e2 * 8 + c];
        const float4 v3 = eattr[(long long)e3 * 8 + c];
        a0.x += v0.x; a0.y += v0.y; a0.z += v0.z; a0.w += v0.w;
        a1.x += v1.x; a1.y += v1.y; a1.z += v1.z; a1.w += v1.w;
        a0.x += v2.x; a0.y += v2.y; a0.z += v2.z; a0.w += v2.w;
        a1.x += v3.x; a1.y += v3.y; a1.z += v3.z; a1.w += v3.w;
    }
    for (; i < end; i += 4) {
        const float4 v = eattr[(long long)g_csr_row_e[i] * 8 + c];
        a0.x += v.x; a0.y += v.y; a0.z += v.z; a0.w += v.w;
    }
    a0.x += a1.x; a0.y += a1.y; a0.z += a1.z; a0.w += a1.w;
#pragma unroll
    for (int off = 8; off <= 16; off <<= 1) {
        a0.x += __shfl_xor_sync(0xffffffffu, a0.x, off);
        a0.y += __shfl_xor_sync(0xffffffffu, a0.y, off);
        a0.z += __shfl_xor_sync(0xffffffffu, a0.z, off);
        a0.w += __shfl_xor_sync(0xffffffffu, a0.w, off);
    }
    if (lane < 8) g_agg[warp * 8 + c] = a0;
}

// ---------------- 3: restore cursor-zero invariant ---------------------------
__global__ __launch_bounds__(256) void cleanup_kernel() {
    int tid = blockIdx.x * blockDim.x + threadIdx.x;
    if (tid < NN) { g_cur_row[tid] = 0; g_cur_col[tid] = 0; }
}

// ---------------- GEMM (f32x2): h' = dinv * ([A|agg] @ W), stored fp16 -------
template <int OC, int CA, bool RELU, bool SRC_OUT1>
__global__ __launch_bounds__(256) void gemm_kernel(const float* __restrict__ Aext) {
    constexpr int K = CA + FE;              // 160
    constexpr int K4 = K / 4;               // 40
    constexpr int CA4 = CA / 4;
    constexpr int TN = 64;
    constexpr int CPT = OC / 64;

    const float4* A4  = SRC_OUT1 ? (const float4*)g_out1 : (const float4*)Aext;
    const float4* WT4 = (OC == 128) ? g_wt1 : g_wt2;
    __half*       Out = (OC == 128) ? g_h1h : g_h2h;

    __shared__ float smk[K * TN];           // 40960 B
    __shared__ float sdeg[TN];
    const int tid = threadIdx.x;
    const long long nb = (long long)blockIdx.x * TN;

    if (tid < TN) {
        const long long node = nb + tid;
        sdeg[tid] = (node < NN) ? g_deg[node] : 0.f;
    }
    for (int idx = tid; idx < TN * CA4; idx += 256) {
        const int n = idx & 63, kk = idx >> 6;
        const long long node = nb + n;
        float4 v = make_float4(0.f, 0.f, 0.f, 0.f);
        if (node < NN) {
            v = A4[node * CA4 + kk];
            if (RELU) {
                v.x = fmaxf(v.x, 0.f); v.y = fmaxf(v.y, 0.f);
                v.z = fmaxf(v.z, 0.f); v.w = fmaxf(v.w, 0.f);
            }
        }
        smk[(4 * kk + 0) * TN + n] = v.x;
        smk[(4 * kk + 1) * TN + n] = v.y;
        smk[(4 * kk + 2) * TN + n] = v.z;
        smk[(4 * kk + 3) * TN + n] = v.w;
    }
    for (int idx = tid; idx < TN * 8; idx += 256) {
        const int n = idx & 63, kk = idx >> 6;
        const long long node = nb + n;
        float4 v = (node < NN) ? g_agg[node * 8 + kk]
                               : make_float4(0.f, 0.f, 0.f, 0.f);
        smk[(CA + 4 * kk + 0) * TN + n] = v.x;
        smk[(CA + 4 * kk + 1) * TN + n] = v.y;
        smk[(CA + 4 * kk + 2) * TN + n] = v.z;
        smk[(CA + 4 * kk + 3) * TN + n] = v.w;
    }
    __syncthreads();

    const int c0  = tid & 63;
    const int seg = tid >> 6;
    unsigned long long acc[CPT][8];
#pragma unroll
    for (int p = 0; p < CPT; ++p)
#pragma unroll
        for (int q = 0; q < 8; ++q) acc[p][q] = 0ull;

    const float* base = smk + seg * 16;
#pragma unroll 2
    for (int k4 = 0; k4 < K4; ++k4) {
        float4 wv[CPT];
#pragma unroll
        for (int p = 0; p < CPT; ++p) wv[p] = WT4[k4 * OC + c0 + 64 * p];
#pragma unroll
        for (int kk = 0; kk < 4; ++kk) {
            const longlong2* rk = (const longlong2*)(base + (4 * k4 + kk) * TN);
            const longlong2 q0 = rk[0];
            const longlong2 q1 = rk[1];
            const longlong2 q2 = rk[2];
            const longlong2 q3 = rk[3];
#pragma unroll
            for (int p = 0; p < CPT; ++p) {
                unsigned long long wp;
                BCAST_F32X2(wp, f4c(wv[p], kk));
                FMA_F32X2(acc[p][0], (unsigned long long)q0.x, wp, acc[p][0]);
                FMA_F32X2(acc[p][1], (unsigned long long)q0.y, wp, acc[p][1]);
                FMA_F32X2(acc[p][2], (unsigned long long)q1.x, wp, acc[p][2]);
                FMA_F32X2(acc[p][3], (unsigned long long)q1.y, wp, acc[p][3]);
                FMA_F32X2(acc[p][4], (unsigned long long)q2.x, wp, acc[p][4]);
                FMA_F32X2(acc[p][5], (unsigned long long)q2.y, wp, acc[p][5]);
                FMA_F32X2(acc[p][6], (unsigned long long)q3.x, wp, acc[p][6]);
                FMA_F32X2(acc[p][7], (unsigned long long)q3.y, wp, acc[p][7]);
            }
        }
    }

#pragma unroll
    for (int q = 0; q < 8; ++q) {
        const long long n0 = nb + seg * 16 + 2 * q;
        unsigned long long dd;
        PACK_F32X2(dd, sdeg[seg * 16 + 2 * q], sdeg[seg * 16 + 2 * q + 1]);
#pragma unroll
        for (int p = 0; p < CPT; ++p) {
            unsigned long long sc;
            MUL_F32X2(sc, acc[p][q], dd);
            unsigned int lo, hi;
            UNPACK_F32X2(lo, hi, sc);
            if (n0 < NN)
                Out[n0 * OC + c0 + 64 * p] = __float2half_rn(__uint_as_float(lo));
            if (n0 + 1 < NN)
                Out[(n0 + 1) * OC + c0 + 64 * p] = __float2half_rn(__uint_as_float(hi));
        }
    }
}

// ---------------- 5: gather 128-dim (fp16 rows, fp32 accumulate) -------------
// out1[n] = b1 + dinv[n] * (h1'[n] + sum_{s in col-CSR[n]} h1'[s])
__global__ __launch_bounds__(256) void gather128_kernel(const float* __restrict__ bias) {
    const uint2* h = (const uint2*)g_h1h;   // row = 32 uint2 (128 halves, 256 B)
    float4* out = g_out1;
    const int n = (blockIdx.x * blockDim.x + threadIdx.x) >> 5;
    if (n >= NN) return;
    const int lane = threadIdx.x & 31;
    const int beg = g_base_col[n], end = g_base_col[n + 1];
    float4 acc0 = make_float4(0.f, 0.f, 0.f, 0.f);
    float4 acc1 = make_float4(0.f, 0.f, 0.f, 0.f);
    for (int i0 = beg; i0 < end; i0 += 32) {
        const int slot = i0 + lane;
        const int s = (slot < end) ? g_csr_col_src[slot] : 0;
        const int m = min(32, end - i0);
        int j = 0;
        for (; j + 4 <= m; j += 4) {
            const int s0 = __shfl_sync(0xffffffffu, s, j);
            const int s1 = __shfl_sync(0xffffffffu, s, j + 1);
            const int s2 = __shfl_sync(0xffffffffu, s, j + 2);
            const int s3 = __shfl_sync(0xffffffffu, s, j + 3);
            const uint2 u0 = h[(long long)s0 * 32 + lane];
            const uint2 u1 = h[(long long)s1 * 32 + lane];
            const uint2 u2 = h[(long long)s2 * 32 + lane];
            const uint2 u3 = h[(long long)s3 * 32 + lane];
            acc_h4(acc0, u0); acc_h4(acc1, u1);
            acc_h4(acc0, u2); acc_h4(acc1, u3);
        }
        for (; j < m; ++j) {
            const int s0 = __shfl_sync(0xffffffffu, s, j);
            acc_h4(acc0, h[(long long)s0 * 32 + lane]);
        }
    }
    acc0.x += acc1.x; acc0.y += acc1.y; acc0.z += acc1.z; acc0.w += acc1.w;
    acc_h4(acc0, h[(long long)n * 32 + lane]);      // self term
    const float dn = g_deg[n];
    const float4 bb = ((const float4*)bias)[lane];
    float4 o;
    o.x = bb.x + dn * acc0.x;
    o.y = bb.y + dn * acc0.y;
    o.z = bb.z + dn * acc0.z;
    o.w = bb.w + dn * acc0.w;
    out[(long long)n * 32 + lane] = o;
}

// ---------------- 7: gather 64-dim (fp16 rows) -------------------------------
__global__ __launch_bounds__(256) void gather64_kernel(const float* __restrict__ bias,
                                                       float4* __restrict__ out) {
    const uint2* h = (const uint2*)g_h2h;   // row = 16 uint2 (64 halves, 128 B)
    const int n = (blockIdx.x * blockDim.x + threadIdx.x) >> 5;
    if (n >= NN) return;
    const int lane = threadIdx.x & 31;
    const int c = lane & 15;
    const int g = lane >> 4;
    const int beg = g_base_col[n], end = g_base_col[n + 1];
    float4 acc0 = make_float4(0.f, 0.f, 0.f, 0.f);
    float4 acc1 = make_float4(0.f, 0.f, 0.f, 0.f);
    for (int i0 = beg; i0 < end; i0 += 32) {
        const int slot = i0 + lane;
        const int s = (slot < end) ? g_csr_col_src[slot] : 0;
        const int m = min(32, end - i0);
        int j = 0;
        for (; j + 8 <= m; j += 8) {
            const int s0 = __shfl_sync(0xffffffffu, s, j + g);
            const int s1 = __shfl_sync(0xffffffffu, s, j + 2 + g);
            const int s2 = __shfl_sync(0xffffffffu, s, j + 4 + g);
            const int s3 = __shfl_sync(0xffffffffu, s, j + 6 + g);
            const uint2 u0 = h[(long long)s0 * 16 + c];
            const uint2 u1 = h[(long long)s1 * 16 + c];
            const uint2 u2 = h[(long long)s2 * 16 + c];
            const uint2 u3 = h[(long long)s3 * 16 + c];
            acc_h4(acc0, u0); acc_h4(acc1, u1);
            acc_h4(acc0, u2); acc_h4(acc1, u3);
        }
        for (; j < m; j += 2) {
            const int idx = j + g;
            const int idxc = min(idx, m - 1);
            const int s0 = __shfl_sync(0xffffffffu, s, idxc);
            const uint2 u = h[(long long)s0 * 16 + c];
            if (idx < m) acc_h4(acc0, u);
        }
    }
    acc0.x += acc1.x; acc0.y += acc1.y; acc0.z += acc1.z; acc0.w += acc1.w;
    acc0.x += __shfl_xor_sync(0xffffffffu, acc0.x, 16);
    acc0.y += __shfl_xor_sync(0xffffffffu, acc0.y, 16);
    acc0.z += __shfl_xor_sync(0xffffffffu, acc0.z, 16);
    acc0.w += __shfl_xor_sync(0xffffffffu, acc0.w, 16);
    if (lane < 16) {
        acc_h4(acc0, h[(long long)n * 16 + c]);     // self term
        const float dn = g_deg[n];
        const float4 bb = ((const float4*)bias)[c];
        float4 o;
        o.x = bb.x + dn * acc0.x;
        o.y = bb.y + dn * acc0.y;
        o.z = bb.z + dn * acc0.z;
        o.w = bb.w + dn * acc0.w;
        out[(long long)n * 16 + c] = o;
    }
}

// ---------------- launch -----------------------------------------------------
extern "C" void kernel_launch(void* const* d_in, const int* in_sizes, int n_in,
                              void* d_out, int out_size) {
    const float*  x    = (const float*)d_in[0];
    const void*   ei   = d_in[1];
    const float4* eatt = (const float4*)d_in[2];
    const float*  w1   = (const float*)d_in[3];
    const float*  b1   = (const float*)d_in[4];
    const float*  w2   = (const float*)d_in[5];
    const float*  b2   = (const float*)d_in[6];
    float* out = (float*)d_out;

    constexpr int T = 256;
    const unsigned gblocks = (NN + 63) / 64;            // 1563
    const unsigned cleanb  = (NN + T - 1) / T;          // 391

    prep_kernel<<<NB, T>>>(ei, w1, w2);                         // 1: CSR prep
    agg_gather_kernel<<<WBLOCKS, T>>>(eatt);                    // 2
    cleanup_kernel<<<cleanb, T>>>();                            // 3 (cursor zero)
    gemm_kernel<HID, FN, false, false><<<gblocks, T>>>(x);      // 4  <- PROFILED
    gather128_kernel<<<WBLOCKS, T>>>(b1);                       // 5
    gemm_kernel<OUTC, HID, true, true><<<gblocks, T>>>(x);      // 6
    gather64_kernel<<<WBLOCKS, T>>>(b2, (float4*)out);          // 7
}